// round 4
// baseline (speedup 1.0000x reference)
#include <cuda_runtime.h>
#include <math.h>

#define NPIX 16384            // 128*128
#define H2 128
#define W2 128

// ---------------------------------------------------------------------------
// Scratch (static device globals)
// ---------------------------------------------------------------------------
__device__ float g_ys [2 * 384 * NPIX];     // stem output               50 MB
__device__ float g_i2h[2 * 192 * NPIX];     // i2h conv out              25 MB
__device__ float g_h2h[2 * 192 * NPIX];     // ret conv out              25 MB
__device__ float g_f1 [2 *  32 * NPIX];     // combined flow features     4 MB
__device__ float g_f1p[4][2 * 32 * NPIX];   // f1 partial sums           17 MB
__device__ float g_fl [2 *  26 * NPIX];     // flows                    3.4 MB
__device__ float g_flp[2][2 * 32 * NPIX];   // flow partial sums        8.4 MB
__device__ float g_wp [2 * 832 * NPIX];     // warped hidden            109 MB

__device__ __forceinline__ float leaky_f(float x) { return x >= 0.f ? x : 0.2f * x; }

// ---------------------------------------------------------------------------
// Stem: conv 3x3 stride 2 pad 1, (B,6,256,256) -> (B,384,128,128), leaky
// ---------------------------------------------------------------------------
__global__ void stem_k(const float* __restrict__ x, const float* __restrict__ w,
                       const float* __restrict__ bias)
{
    int pix = blockIdx.x * 256 + threadIdx.x;
    int oc0 = blockIdx.y * 4;
    int b   = blockIdx.z;
    int oy = pix >> 7, ox = pix & 127;

    float a0 = bias[oc0 + 0], a1 = bias[oc0 + 1], a2 = bias[oc0 + 2], a3 = bias[oc0 + 3];

    #pragma unroll
    for (int ic = 0; ic < 6; ic++) {
        const float* xb = x + (b * 6 + ic) * 65536;
        #pragma unroll
        for (int ky = 0; ky < 3; ky++) {
            int iy = 2 * oy - 1 + ky;
            if (iy < 0 || iy > 255) continue;
            #pragma unroll
            for (int kx = 0; kx < 3; kx++) {
                int ix = 2 * ox - 1 + kx;
                if (ix < 0 || ix > 255) continue;
                float v = __ldg(&xb[iy * 256 + ix]);
                int wi = ic * 9 + ky * 3 + kx;
                a0 += v * __ldg(&w[(oc0 + 0) * 54 + wi]);
                a1 += v * __ldg(&w[(oc0 + 1) * 54 + wi]);
                a2 += v * __ldg(&w[(oc0 + 2) * 54 + wi]);
                a3 += v * __ldg(&w[(oc0 + 3) * 54 + wi]);
            }
        }
    }
    g_ys[(b * 384 + oc0 + 0) * NPIX + pix] = leaky_f(a0);
    g_ys[(b * 384 + oc0 + 1) * NPIX + pix] = leaky_f(a1);
    g_ys[(b * 384 + oc0 + 2) * NPIX + pix] = leaky_f(a2);
    g_ys[(b * 384 + oc0 + 3) * NPIX + pix] = leaky_f(a3);
}

// ---------------------------------------------------------------------------
// i2h: conv 3x3 pad 1, 64 -> 192.
// Tile 32x64 pixels, 256 threads, each: 8 oc x 8 x-pixels (64 acc).
// Weights transposed in smem [ic][k][oc8] -> vector broadcast loads.
// grid (8, 24, 2)
// ---------------------------------------------------------------------------
__global__ __launch_bounds__(256) void i2h_k(int t, const float* __restrict__ w,
                                             const float* __restrict__ bias)
{
    __shared__ __align__(16) float s_in[4][66][36];
    __shared__ __align__(16) float s_w [4][9][8];

    int tid = threadIdx.x;
    int tx = tid & 3, ty = tid >> 2;           // tx: x-group of 8, ty: row
    int xt0 = (blockIdx.x & 3) * 32;
    int yt0 = (blockIdx.x >> 2) * 64;
    int oc0 = blockIdx.y * 8;
    int b   = blockIdx.z;
    const float* in = g_ys + (b * 384 + t * 64) * NPIX;

    float acc[8][8];
    #pragma unroll
    for (int j = 0; j < 8; j++) {
        float bv = bias[oc0 + j];
        #pragma unroll
        for (int p = 0; p < 8; p++) acc[j][p] = bv;
    }

    for (int c0 = 0; c0 < 64; c0 += 4) {
        for (int i = tid; i < 288; i += 256) {
            int ic = i / 72, r = i % 72, k = r >> 3, j = r & 7;
            s_w[ic][k][j] = w[((oc0 + j) * 64 + c0 + ic) * 9 + k];
        }
        for (int i = tid; i < 4 * 66 * 36; i += 256) {
            int ic = i / 2376, r = i % 2376, ly = r / 36, lx = r % 36;
            int gy = yt0 + ly - 1, gx = xt0 + lx - 1;
            float v = 0.f;
            if (lx < 34 && gy >= 0 && gy < 128 && gx >= 0 && gx < 128)
                v = in[(c0 + ic) * NPIX + gy * 128 + gx];
            s_in[ic][ly][lx] = v;
        }
        __syncthreads();

        #pragma unroll 1
        for (int ic = 0; ic < 4; ic++) {
            #pragma unroll
            for (int ky = 0; ky < 3; ky++) {
                float bb[12];
                *(float4*)&bb[0] = *(const float4*)&s_in[ic][ty + ky][tx * 8];
                *(float4*)&bb[4] = *(const float4*)&s_in[ic][ty + ky][tx * 8 + 4];
                *(float4*)&bb[8] = *(const float4*)&s_in[ic][ty + ky][tx * 8 + 8];
                #pragma unroll
                for (int kx = 0; kx < 3; kx++) {
                    float a[8];
                    *(float4*)&a[0] = *(const float4*)&s_w[ic][ky * 3 + kx][0];
                    *(float4*)&a[4] = *(const float4*)&s_w[ic][ky * 3 + kx][4];
                    #pragma unroll
                    for (int j = 0; j < 8; j++)
                        #pragma unroll
                        for (int p = 0; p < 8; p++)
                            acc[j][p] += a[j] * bb[kx + p];
                }
            }
        }
        __syncthreads();
    }

    int pix = (yt0 + ty) * 128 + xt0 + tx * 8;
    #pragma unroll
    for (int j = 0; j < 8; j++) {
        float* o = &g_i2h[(b * 192 + oc0 + j) * NPIX + pix];
        *(float4*)&o[0] = *(float4*)&acc[j][0];
        *(float4*)&o[4] = *(float4*)&acc[j][4];
    }
}

// ---------------------------------------------------------------------------
// f1: conv5x5(xt) + conv5x5(hprev), computed as 4 partial sums (2 src x 2
// channel halves) into g_f1p[csplit]. No bias/activation here (see f1comb).
// grid (8, 16, 2): blockIdx.y = csplit*4 + ocg
// ---------------------------------------------------------------------------
__global__ __launch_bounds__(256) void f1_k(int t, int first,
                                            const float* __restrict__ wi,
                                            const float* __restrict__ wh,
                                            const float* __restrict__ outp)
{
    __shared__ __align__(16) float s_in[4][68][40];
    __shared__ __align__(16) float s_w [4][25][8];

    int csplit = blockIdx.y >> 2;
    int src    = csplit >> 1;
    if (first && src) return;                  // hprev == 0 at t=0
    int oc0   = (blockIdx.y & 3) * 8;
    int cbase = (csplit & 1) * 32;

    int tid = threadIdx.x;
    int tx = tid & 3, ty = tid >> 2;
    int xt0 = (blockIdx.x & 3) * 32;
    int yt0 = (blockIdx.x >> 2) * 64;
    int b   = blockIdx.z;

    const float* in = src ? (outp + ((b * 6 + (t - 1)) * 64 + cbase) * NPIX)
                          : (g_ys + (b * 384 + t * 64 + cbase) * NPIX);
    const float* w  = src ? wh : wi;

    float acc[8][8];
    #pragma unroll
    for (int j = 0; j < 8; j++)
        #pragma unroll
        for (int p = 0; p < 8; p++) acc[j][p] = 0.f;

    for (int c0 = 0; c0 < 32; c0 += 4) {
        for (int i = tid; i < 800; i += 256) {
            int ic = i / 200, r = i % 200, k = r >> 3, j = r & 7;
            s_w[ic][k][j] = w[((oc0 + j) * 64 + cbase + c0 + ic) * 25 + k];
        }
        for (int i = tid; i < 4 * 68 * 40; i += 256) {
            int ic = i / 2720, r = i % 2720, ly = r / 40, lx = r % 40;
            int gy = yt0 + ly - 2, gx = xt0 + lx - 2;
            float v = 0.f;
            if (lx < 36 && gy >= 0 && gy < 128 && gx >= 0 && gx < 128)
                v = in[(c0 + ic) * NPIX + gy * 128 + gx];
            s_in[ic][ly][lx] = v;
        }
        __syncthreads();

        #pragma unroll 1
        for (int ic = 0; ic < 4; ic++) {
            #pragma unroll 1
            for (int ky = 0; ky < 5; ky++) {
                float bb[12];
                *(float4*)&bb[0] = *(const float4*)&s_in[ic][ty + ky][tx * 8];
                *(float4*)&bb[4] = *(const float4*)&s_in[ic][ty + ky][tx * 8 + 4];
                *(float4*)&bb[8] = *(const float4*)&s_in[ic][ty + ky][tx * 8 + 8];
                #pragma unroll
                for (int kx = 0; kx < 5; kx++) {
                    float a[8];
                    *(float4*)&a[0] = *(const float4*)&s_w[ic][ky * 5 + kx][0];
                    *(float4*)&a[4] = *(const float4*)&s_w[ic][ky * 5 + kx][4];
                    #pragma unroll
                    for (int j = 0; j < 8; j++)
                        #pragma unroll
                        for (int p = 0; p < 8; p++)
                            acc[j][p] += a[j] * bb[kx + p];
                }
            }
        }
        __syncthreads();
    }

    int pix = (yt0 + ty) * 128 + xt0 + tx * 8;
    float* op = g_f1p[csplit];
    #pragma unroll
    for (int j = 0; j < 8; j++) {
        float* o = &op[(b * 32 + oc0 + j) * NPIX + pix];
        *(float4*)&o[0] = *(float4*)&acc[j][0];
        *(float4*)&o[4] = *(float4*)&acc[j][4];
    }
}

// f1 combine: sum partials + both biases, leaky -> g_f1
__global__ void f1comb_k(const float* __restrict__ bi, const float* __restrict__ bh, int first)
{
    int idx = blockIdx.x * 256 + threadIdx.x;       // over 2*32*NPIX
    int c = (idx >> 14) & 31;
    float v = g_f1p[0][idx] + g_f1p[1][idx];
    if (!first) v += g_f1p[2][idx] + g_f1p[3][idx];
    v += bi[c] + bh[c];
    g_f1[idx] = leaky_f(v);
}

// ---------------------------------------------------------------------------
// flow: conv 5x5 pad 2, 32 -> 26 (padded to 32 oc), 2 channel-half partials.
// grid (8, 8, 2): blockIdx.y = csplit*4 + ocg
// ---------------------------------------------------------------------------
__global__ __launch_bounds__(256) void flow_k(const float* __restrict__ w)
{
    __shared__ __align__(16) float s_in[4][68][40];
    __shared__ __align__(16) float s_w [4][25][8];

    int csplit = blockIdx.y >> 2;                  // 0..1
    int oc0    = (blockIdx.y & 3) * 8;             // 0,8,16,24
    int cbase  = csplit * 16;

    int tid = threadIdx.x;
    int tx = tid & 3, ty = tid >> 2;
    int xt0 = (blockIdx.x & 3) * 32;
    int yt0 = (blockIdx.x >> 2) * 64;
    int b   = blockIdx.z;
    const float* in = g_f1 + (b * 32 + cbase) * NPIX;

    float acc[8][8];
    #pragma unroll
    for (int j = 0; j < 8; j++)
        #pragma unroll
        for (int p = 0; p < 8; p++) acc[j][p] = 0.f;

    for (int c0 = 0; c0 < 16; c0 += 4) {
        for (int i = tid; i < 800; i += 256) {
            int ic = i / 200, r = i % 200, k = r >> 3, j = r & 7;
            s_w[ic][k][j] = (oc0 + j < 26)
                ? w[((oc0 + j) * 32 + cbase + c0 + ic) * 25 + k] : 0.f;
        }
        for (int i = tid; i < 4 * 68 * 40; i += 256) {
            int ic = i / 2720, r = i % 2720, ly = r / 40, lx = r % 40;
            int gy = yt0 + ly - 2, gx = xt0 + lx - 2;
            float v = 0.f;
            if (lx < 36 && gy >= 0 && gy < 128 && gx >= 0 && gx < 128)
                v = in[(c0 + ic) * NPIX + gy * 128 + gx];
            s_in[ic][ly][lx] = v;
        }
        __syncthreads();

        #pragma unroll 1
        for (int ic = 0; ic < 4; ic++) {
            #pragma unroll 1
            for (int ky = 0; ky < 5; ky++) {
                float bb[12];
                *(float4*)&bb[0] = *(const float4*)&s_in[ic][ty + ky][tx * 8];
                *(float4*)&bb[4] = *(const float4*)&s_in[ic][ty + ky][tx * 8 + 4];
                *(float4*)&bb[8] = *(const float4*)&s_in[ic][ty + ky][tx * 8 + 8];
                #pragma unroll
                for (int kx = 0; kx < 5; kx++) {
                    float a[8];
                    *(float4*)&a[0] = *(const float4*)&s_w[ic][ky * 5 + kx][0];
                    *(float4*)&a[4] = *(const float4*)&s_w[ic][ky * 5 + kx][4];
                    #pragma unroll
                    for (int j = 0; j < 8; j++)
                        #pragma unroll
                        for (int p = 0; p < 8; p++)
                            acc[j][p] += a[j] * bb[kx + p];
                }
            }
        }
        __syncthreads();
    }

    int pix = (yt0 + ty) * 128 + xt0 + tx * 8;
    float* op = g_flp[csplit];
    #pragma unroll
    for (int j = 0; j < 8; j++) {
        float* o = &op[(b * 32 + oc0 + j) * NPIX + pix];
        *(float4*)&o[0] = *(float4*)&acc[j][0];
        *(float4*)&o[4] = *(float4*)&acc[j][4];
    }
}

// flow combine: sum 2 partials + bias -> g_fl (26 channels)
__global__ void flowcomb_k(const float* __restrict__ bias)
{
    int idx = blockIdx.x * 256 + threadIdx.x;       // over 2*26*NPIX
    if (idx >= 2 * 26 * NPIX) return;
    int b = idx / (26 * NPIX);
    int r = idx - b * (26 * NPIX);
    int c = r >> 14;
    int pix = r & (NPIX - 1);
    int pi = (b * 32 + c) * NPIX + pix;
    g_fl[idx] = g_flp[0][pi] + g_flp[1][pi] + bias[c];
}

// ---------------------------------------------------------------------------
// warp: bilinear sample hprev at (x-u, y-v), 13 flows x 64 ch.
// ---------------------------------------------------------------------------
__global__ void warp_k(int t, const float* __restrict__ outp)
{
    int pix = blockIdx.x * 256 + threadIdx.x;
    int l   = blockIdx.y;
    int b   = blockIdx.z;

    float u = g_fl[(b * 26 + 2 * l + 0) * NPIX + pix];
    float v = g_fl[(b * 26 + 2 * l + 1) * NPIX + pix];
    float sx = (float)(pix & 127) - u;
    float sy = (float)(pix >> 7)  - v;

    float fx = floorf(sx), fy = floorf(sy);
    float wx1 = sx - fx, wx0 = 1.f - wx1;
    float wy1 = sy - fy, wy0 = 1.f - wy1;
    int x0 = (int)fx, y0 = (int)fy;
    int x1 = x0 + 1,  y1 = y0 + 1;

    bool vx0 = (x0 >= 0) & (x0 <= 127);
    bool vx1 = (x1 >= 0) & (x1 <= 127);
    bool vy0 = (y0 >= 0) & (y0 <= 127);
    bool vy1 = (y1 >= 0) & (y1 <= 127);

    int cx0 = min(max(x0, 0), 127), cx1 = min(max(x1, 0), 127);
    int cy0 = min(max(y0, 0), 127), cy1 = min(max(y1, 0), 127);

    int i00 = cy0 * 128 + cx0, i10 = cy0 * 128 + cx1;
    int i01 = cy1 * 128 + cx0, i11 = cy1 * 128 + cx1;

    float w00 = (vx0 && vy0) ? wx0 * wy0 : 0.f;
    float w10 = (vx1 && vy0) ? wx1 * wy0 : 0.f;
    float w01 = (vx0 && vy1) ? wx0 * wy1 : 0.f;
    float w11 = (vx1 && vy1) ? wx1 * wy1 : 0.f;

    const float* hp = outp + ((b * 6 + (t - 1)) * 64) * NPIX;
    float* wp = g_wp + ((b * 13 + l) * 64) * NPIX + pix;

    #pragma unroll 4
    for (int c = 0; c < 64; c++) {
        const float* hc = hp + c * NPIX;
        float val = w00 * __ldg(&hc[i00]) + w10 * __ldg(&hc[i10])
                  + w01 * __ldg(&hc[i01]) + w11 * __ldg(&hc[i11]);
        wp[c * NPIX] = val;
    }
}

// ---------------------------------------------------------------------------
// ret: SGEMM C[192,16384] = W[192,832] * X[832,16384] + bias, per batch.
// BM=64, BN=256, BK=16, 256 threads, 4x16 spread microtile. grid (64,3,2).
// ---------------------------------------------------------------------------
__global__ __launch_bounds__(256) void ret_k(const float* __restrict__ W,
                                             const float* __restrict__ bias, int first)
{
    __shared__ __align__(16) float As[16][68];
    __shared__ __align__(16) float Bs[16][256];

    int tid = threadIdx.x;
    int b  = blockIdx.z;
    int n0 = blockIdx.x * 256;
    int m0 = blockIdx.y * 64;
    int tm = tid >> 4, tn = tid & 15;
    const float* X = g_wp + b * 832 * NPIX;

    float acc[4][16];
    #pragma unroll
    for (int i = 0; i < 4; i++)
        #pragma unroll
        for (int c = 0; c < 16; c++) acc[i][c] = 0.f;

    int nk = first ? 0 : 52;
    for (int kt = 0; kt < nk; kt++) {
        int k0 = kt * 16;
        #pragma unroll
        for (int r = 0; r < 4; r++) {
            int i = tid + r * 256;
            int m = i >> 4, k = i & 15;
            As[k][m] = W[(m0 + m) * 832 + k0 + k];
        }
        #pragma unroll
        for (int r = 0; r < 4; r++) {
            int fi = tid + r * 256;
            int kb = fi >> 6, nf = fi & 63;
            *(float4*)&Bs[kb][nf * 4] = *(const float4*)&X[(k0 + kb) * NPIX + n0 + nf * 4];
        }
        __syncthreads();

        #pragma unroll
        for (int kk = 0; kk < 16; kk++) {
            float a[4];
            *(float4*)&a[0] = *(const float4*)&As[kk][tm * 4];
            #pragma unroll
            for (int g = 0; g < 4; g++) {
                float4 bv = *(const float4*)&Bs[kk][g * 64 + tn * 4];
                #pragma unroll
                for (int i = 0; i < 4; i++) {
                    acc[i][g * 4 + 0] += a[i] * bv.x;
                    acc[i][g * 4 + 1] += a[i] * bv.y;
                    acc[i][g * 4 + 2] += a[i] * bv.z;
                    acc[i][g * 4 + 3] += a[i] * bv.w;
                }
            }
        }
        __syncthreads();
    }

    float* C = g_h2h + b * 192 * NPIX;
    #pragma unroll
    for (int i = 0; i < 4; i++) {
        int m = m0 + tm * 4 + i;
        float bb = bias[m];
        #pragma unroll
        for (int g = 0; g < 4; g++) {
            float4 o = make_float4(acc[i][g * 4 + 0] + bb, acc[i][g * 4 + 1] + bb,
                                   acc[i][g * 4 + 2] + bb, acc[i][g * 4 + 3] + bb);
            *(float4*)&C[m * NPIX + n0 + g * 64 + tn * 4] = o;
        }
    }
}

// ---------------------------------------------------------------------------
// GRU elementwise update; writes out[b, t].
// ---------------------------------------------------------------------------
__global__ void gru_k(int t, int first, float* __restrict__ outp)
{
    int pix = blockIdx.x * 256 + threadIdx.x;
    int c   = blockIdx.y;
    int b   = blockIdx.z;
    int base = b * 192 * NPIX;

    float ir = g_i2h[base + (c      ) * NPIX + pix];
    float iu = g_i2h[base + (c +  64) * NPIX + pix];
    float im = g_i2h[base + (c + 128) * NPIX + pix];
    float hr = g_h2h[base + (c      ) * NPIX + pix];
    float hu = g_h2h[base + (c +  64) * NPIX + pix];
    float hm = g_h2h[base + (c + 128) * NPIX + pix];

    float r = 1.f / (1.f + expf(-(ir + hr)));
    float z = 1.f / (1.f + expf(-(iu + hu)));
    float m = leaky_f(im + r * hm);

    float hp = first ? 0.f : outp[((b * 6 + t - 1) * 64 + c) * NPIX + pix];
    outp[((b * 6 + t) * 64 + c) * NPIX + pix] = z * hp + (1.f - z) * m;
}

// ---------------------------------------------------------------------------
// Launch
// ---------------------------------------------------------------------------
extern "C" void kernel_launch(void* const* d_in, const int* in_sizes, int n_in,
                              void* d_out, int out_size)
{
    const float* x      = (const float*)d_in[0];
    const float* w_stem = (const float*)d_in[1];
    const float* b_stem = (const float*)d_in[2];
    const float* w_i2h  = (const float*)d_in[3];
    const float* b_i2h  = (const float*)d_in[4];
    const float* w_i2f  = (const float*)d_in[5];
    const float* b_i2f  = (const float*)d_in[6];
    const float* w_h2f  = (const float*)d_in[7];
    const float* b_h2f  = (const float*)d_in[8];
    const float* w_flow = (const float*)d_in[9];
    const float* b_flow = (const float*)d_in[10];
    const float* w_ret  = (const float*)d_in[11];
    const float* b_ret  = (const float*)d_in[12];
    float* outp = (float*)d_out;

    stem_k<<<dim3(64, 96, 2), 256>>>(x, w_stem, b_stem);

    for (int t = 0; t < 6; t++) {
        int first = (t == 0) ? 1 : 0;
        i2h_k   <<<dim3(8, 24, 2), 256>>>(t, w_i2h, b_i2h);
        f1_k    <<<dim3(8, 16, 2), 256>>>(t, first, w_i2f, w_h2f, outp);
        f1comb_k<<<(2 * 32 * NPIX) / 256, 256>>>(b_i2f, b_h2f, first);
        flow_k  <<<dim3(8, 8, 2), 256>>>(w_flow);
        flowcomb_k<<<(2 * 26 * NPIX + 255) / 256, 256>>>(b_flow);
        if (!first)
            warp_k<<<dim3(64, 13, 2), 256>>>(t, outp);
        ret_k   <<<dim3(64, 3, 2), 256>>>(w_ret, b_ret, first);
        gru_k   <<<dim3(64, 64, 2), 256>>>(t, first, outp);
    }
}

// round 5
// speedup vs baseline: 1.1162x; 1.1162x over previous
#include <cuda_runtime.h>
#include <math.h>
#include <stdint.h>

#define NPIX 16384            // 128*128
#define H2 128
#define W2 128

// ---------------------------------------------------------------------------
// Scratch (static device globals)
// ---------------------------------------------------------------------------
__device__ float g_ys [2 * 384 * NPIX];     // stem output               50 MB
__device__ float g_i2h[2 * 192 * NPIX];     // i2h conv out              25 MB
__device__ float g_h2h[2 * 192 * NPIX];     // ret conv out              25 MB
__device__ float g_f1 [2 *  32 * NPIX];     // combined flow features     4 MB
__device__ float g_f1p[4][2 * 32 * NPIX];   // f1 partial sums           17 MB
__device__ float g_fl [2 *  26 * NPIX];     // flows                    3.4 MB
__device__ float g_flp[2][2 * 32 * NPIX];   // flow partial sums        8.4 MB
__device__ float g_wp [2 * 832 * NPIX];     // warped hidden            109 MB

__device__ __forceinline__ float leaky_f(float x) { return x >= 0.f ? x : 0.2f * x; }

__device__ __forceinline__ uint32_t f2tf32(float x) {
    uint32_t r;
    asm("cvt.rna.tf32.f32 %0, %1;" : "=r"(r) : "f"(x));
    return r;
}

#define MMA_TF32(c0,c1,c2,c3, a0,a1,a2,a3, b0,b1)                              \
    asm volatile("mma.sync.aligned.m16n8k8.row.col.f32.tf32.tf32.f32 "         \
        "{%0,%1,%2,%3}, {%4,%5,%6,%7}, {%8,%9}, {%0,%1,%2,%3};"                \
        : "+f"(c0), "+f"(c1), "+f"(c2), "+f"(c3)                               \
        : "r"(a0), "r"(a1), "r"(a2), "r"(a3), "r"(b0), "r"(b1))

// ---------------------------------------------------------------------------
// Stem: conv 3x3 stride 2 pad 1, (B,6,256,256) -> (B,384,128,128), leaky
// ---------------------------------------------------------------------------
__global__ void stem_k(const float* __restrict__ x, const float* __restrict__ w,
                       const float* __restrict__ bias)
{
    int pix = blockIdx.x * 256 + threadIdx.x;
    int oc0 = blockIdx.y * 4;
    int b   = blockIdx.z;
    int oy = pix >> 7, ox = pix & 127;

    float a0 = bias[oc0 + 0], a1 = bias[oc0 + 1], a2 = bias[oc0 + 2], a3 = bias[oc0 + 3];

    #pragma unroll
    for (int ic = 0; ic < 6; ic++) {
        const float* xb = x + (b * 6 + ic) * 65536;
        #pragma unroll
        for (int ky = 0; ky < 3; ky++) {
            int iy = 2 * oy - 1 + ky;
            if (iy < 0 || iy > 255) continue;
            #pragma unroll
            for (int kx = 0; kx < 3; kx++) {
                int ix = 2 * ox - 1 + kx;
                if (ix < 0 || ix > 255) continue;
                float v = __ldg(&xb[iy * 256 + ix]);
                int wi = ic * 9 + ky * 3 + kx;
                a0 += v * __ldg(&w[(oc0 + 0) * 54 + wi]);
                a1 += v * __ldg(&w[(oc0 + 1) * 54 + wi]);
                a2 += v * __ldg(&w[(oc0 + 2) * 54 + wi]);
                a3 += v * __ldg(&w[(oc0 + 3) * 54 + wi]);
            }
        }
    }
    g_ys[(b * 384 + oc0 + 0) * NPIX + pix] = leaky_f(a0);
    g_ys[(b * 384 + oc0 + 1) * NPIX + pix] = leaky_f(a1);
    g_ys[(b * 384 + oc0 + 2) * NPIX + pix] = leaky_f(a2);
    g_ys[(b * 384 + oc0 + 3) * NPIX + pix] = leaky_f(a3);
}

// ---------------------------------------------------------------------------
// i2h: conv 3x3 pad 1, 64 -> 192. (unchanged from round 2)
// ---------------------------------------------------------------------------
__global__ __launch_bounds__(256) void i2h_k(int t, const float* __restrict__ w,
                                             const float* __restrict__ bias)
{
    __shared__ __align__(16) float s_in[4][66][36];
    __shared__ __align__(16) float s_w [4][9][8];

    int tid = threadIdx.x;
    int tx = tid & 3, ty = tid >> 2;
    int xt0 = (blockIdx.x & 3) * 32;
    int yt0 = (blockIdx.x >> 2) * 64;
    int oc0 = blockIdx.y * 8;
    int b   = blockIdx.z;
    const float* in = g_ys + (b * 384 + t * 64) * NPIX;

    float acc[8][8];
    #pragma unroll
    for (int j = 0; j < 8; j++) {
        float bv = bias[oc0 + j];
        #pragma unroll
        for (int p = 0; p < 8; p++) acc[j][p] = bv;
    }

    for (int c0 = 0; c0 < 64; c0 += 4) {
        for (int i = tid; i < 288; i += 256) {
            int ic = i / 72, r = i % 72, k = r >> 3, j = r & 7;
            s_w[ic][k][j] = w[((oc0 + j) * 64 + c0 + ic) * 9 + k];
        }
        for (int i = tid; i < 4 * 66 * 36; i += 256) {
            int ic = i / 2376, r = i % 2376, ly = r / 36, lx = r % 36;
            int gy = yt0 + ly - 1, gx = xt0 + lx - 1;
            float v = 0.f;
            if (lx < 34 && gy >= 0 && gy < 128 && gx >= 0 && gx < 128)
                v = in[(c0 + ic) * NPIX + gy * 128 + gx];
            s_in[ic][ly][lx] = v;
        }
        __syncthreads();

        #pragma unroll 1
        for (int ic = 0; ic < 4; ic++) {
            #pragma unroll
            for (int ky = 0; ky < 3; ky++) {
                float bb[12];
                *(float4*)&bb[0] = *(const float4*)&s_in[ic][ty + ky][tx * 8];
                *(float4*)&bb[4] = *(const float4*)&s_in[ic][ty + ky][tx * 8 + 4];
                *(float4*)&bb[8] = *(const float4*)&s_in[ic][ty + ky][tx * 8 + 8];
                #pragma unroll
                for (int kx = 0; kx < 3; kx++) {
                    float a[8];
                    *(float4*)&a[0] = *(const float4*)&s_w[ic][ky * 3 + kx][0];
                    *(float4*)&a[4] = *(const float4*)&s_w[ic][ky * 3 + kx][4];
                    #pragma unroll
                    for (int j = 0; j < 8; j++)
                        #pragma unroll
                        for (int p = 0; p < 8; p++)
                            acc[j][p] += a[j] * bb[kx + p];
                }
            }
        }
        __syncthreads();
    }

    int pix = (yt0 + ty) * 128 + xt0 + tx * 8;
    #pragma unroll
    for (int j = 0; j < 8; j++) {
        float* o = &g_i2h[(b * 192 + oc0 + j) * NPIX + pix];
        *(float4*)&o[0] = *(float4*)&acc[j][0];
        *(float4*)&o[4] = *(float4*)&acc[j][4];
    }
}

// ---------------------------------------------------------------------------
// f1: conv5x5(xt) + conv5x5(hprev) as 4 partial sums. (unchanged)
// ---------------------------------------------------------------------------
__global__ __launch_bounds__(256) void f1_k(int t, int first,
                                            const float* __restrict__ wi,
                                            const float* __restrict__ wh,
                                            const float* __restrict__ outp)
{
    __shared__ __align__(16) float s_in[4][68][40];
    __shared__ __align__(16) float s_w [4][25][8];

    int csplit = blockIdx.y >> 2;
    int src    = csplit >> 1;
    if (first && src) return;
    int oc0   = (blockIdx.y & 3) * 8;
    int cbase = (csplit & 1) * 32;

    int tid = threadIdx.x;
    int tx = tid & 3, ty = tid >> 2;
    int xt0 = (blockIdx.x & 3) * 32;
    int yt0 = (blockIdx.x >> 2) * 64;
    int b   = blockIdx.z;

    const float* in = src ? (outp + ((b * 6 + (t - 1)) * 64 + cbase) * NPIX)
                          : (g_ys + (b * 384 + t * 64 + cbase) * NPIX);
    const float* w  = src ? wh : wi;

    float acc[8][8];
    #pragma unroll
    for (int j = 0; j < 8; j++)
        #pragma unroll
        for (int p = 0; p < 8; p++) acc[j][p] = 0.f;

    for (int c0 = 0; c0 < 32; c0 += 4) {
        for (int i = tid; i < 800; i += 256) {
            int ic = i / 200, r = i % 200, k = r >> 3, j = r & 7;
            s_w[ic][k][j] = w[((oc0 + j) * 64 + cbase + c0 + ic) * 25 + k];
        }
        for (int i = tid; i < 4 * 68 * 40; i += 256) {
            int ic = i / 2720, r = i % 2720, ly = r / 40, lx = r % 40;
            int gy = yt0 + ly - 2, gx = xt0 + lx - 2;
            float v = 0.f;
            if (lx < 36 && gy >= 0 && gy < 128 && gx >= 0 && gx < 128)
                v = in[(c0 + ic) * NPIX + gy * 128 + gx];
            s_in[ic][ly][lx] = v;
        }
        __syncthreads();

        #pragma unroll 1
        for (int ic = 0; ic < 4; ic++) {
            #pragma unroll 1
            for (int ky = 0; ky < 5; ky++) {
                float bb[12];
                *(float4*)&bb[0] = *(const float4*)&s_in[ic][ty + ky][tx * 8];
                *(float4*)&bb[4] = *(const float4*)&s_in[ic][ty + ky][tx * 8 + 4];
                *(float4*)&bb[8] = *(const float4*)&s_in[ic][ty + ky][tx * 8 + 8];
                #pragma unroll
                for (int kx = 0; kx < 5; kx++) {
                    float a[8];
                    *(float4*)&a[0] = *(const float4*)&s_w[ic][ky * 5 + kx][0];
                    *(float4*)&a[4] = *(const float4*)&s_w[ic][ky * 5 + kx][4];
                    #pragma unroll
                    for (int j = 0; j < 8; j++)
                        #pragma unroll
                        for (int p = 0; p < 8; p++)
                            acc[j][p] += a[j] * bb[kx + p];
                }
            }
        }
        __syncthreads();
    }

    int pix = (yt0 + ty) * 128 + xt0 + tx * 8;
    float* op = g_f1p[csplit];
    #pragma unroll
    for (int j = 0; j < 8; j++) {
        float* o = &op[(b * 32 + oc0 + j) * NPIX + pix];
        *(float4*)&o[0] = *(float4*)&acc[j][0];
        *(float4*)&o[4] = *(float4*)&acc[j][4];
    }
}

__global__ void f1comb_k(const float* __restrict__ bi, const float* __restrict__ bh, int first)
{
    int idx = blockIdx.x * 256 + threadIdx.x;
    int c = (idx >> 14) & 31;
    float v = g_f1p[0][idx] + g_f1p[1][idx];
    if (!first) v += g_f1p[2][idx] + g_f1p[3][idx];
    v += bi[c] + bh[c];
    g_f1[idx] = leaky_f(v);
}

// ---------------------------------------------------------------------------
// flow: conv 5x5 pad 2, 32 -> 26 (padded to 32 oc). (unchanged)
// ---------------------------------------------------------------------------
__global__ __launch_bounds__(256) void flow_k(const float* __restrict__ w)
{
    __shared__ __align__(16) float s_in[4][68][40];
    __shared__ __align__(16) float s_w [4][25][8];

    int csplit = blockIdx.y >> 2;
    int oc0    = (blockIdx.y & 3) * 8;
    int cbase  = csplit * 16;

    int tid = threadIdx.x;
    int tx = tid & 3, ty = tid >> 2;
    int xt0 = (blockIdx.x & 3) * 32;
    int yt0 = (blockIdx.x >> 2) * 64;
    int b   = blockIdx.z;
    const float* in = g_f1 + (b * 32 + cbase) * NPIX;

    float acc[8][8];
    #pragma unroll
    for (int j = 0; j < 8; j++)
        #pragma unroll
        for (int p = 0; p < 8; p++) acc[j][p] = 0.f;

    for (int c0 = 0; c0 < 16; c0 += 4) {
        for (int i = tid; i < 800; i += 256) {
            int ic = i / 200, r = i % 200, k = r >> 3, j = r & 7;
            s_w[ic][k][j] = (oc0 + j < 26)
                ? w[((oc0 + j) * 32 + cbase + c0 + ic) * 25 + k] : 0.f;
        }
        for (int i = tid; i < 4 * 68 * 40; i += 256) {
            int ic = i / 2720, r = i % 2720, ly = r / 40, lx = r % 40;
            int gy = yt0 + ly - 2, gx = xt0 + lx - 2;
            float v = 0.f;
            if (lx < 36 && gy >= 0 && gy < 128 && gx >= 0 && gx < 128)
                v = in[(c0 + ic) * NPIX + gy * 128 + gx];
            s_in[ic][ly][lx] = v;
        }
        __syncthreads();

        #pragma unroll 1
        for (int ic = 0; ic < 4; ic++) {
            #pragma unroll 1
            for (int ky = 0; ky < 5; ky++) {
                float bb[12];
                *(float4*)&bb[0] = *(const float4*)&s_in[ic][ty + ky][tx * 8];
                *(float4*)&bb[4] = *(const float4*)&s_in[ic][ty + ky][tx * 8 + 4];
                *(float4*)&bb[8] = *(const float4*)&s_in[ic][ty + ky][tx * 8 + 8];
                #pragma unroll
                for (int kx = 0; kx < 5; kx++) {
                    float a[8];
                    *(float4*)&a[0] = *(const float4*)&s_w[ic][ky * 5 + kx][0];
                    *(float4*)&a[4] = *(const float4*)&s_w[ic][ky * 5 + kx][4];
                    #pragma unroll
                    for (int j = 0; j < 8; j++)
                        #pragma unroll
                        for (int p = 0; p < 8; p++)
                            acc[j][p] += a[j] * bb[kx + p];
                }
            }
        }
        __syncthreads();
    }

    int pix = (yt0 + ty) * 128 + xt0 + tx * 8;
    float* op = g_flp[csplit];
    #pragma unroll
    for (int j = 0; j < 8; j++) {
        float* o = &op[(b * 32 + oc0 + j) * NPIX + pix];
        *(float4*)&o[0] = *(float4*)&acc[j][0];
        *(float4*)&o[4] = *(float4*)&acc[j][4];
    }
}

__global__ void flowcomb_k(const float* __restrict__ bias)
{
    int idx = blockIdx.x * 256 + threadIdx.x;
    if (idx >= 2 * 26 * NPIX) return;
    int b = idx / (26 * NPIX);
    int r = idx - b * (26 * NPIX);
    int c = r >> 14;
    int pix = r & (NPIX - 1);
    int pi = (b * 32 + c) * NPIX + pix;
    g_fl[idx] = g_flp[0][pi] + g_flp[1][pi] + bias[c];
}

// ---------------------------------------------------------------------------
// warp: bilinear sample hprev at (x-u, y-v), 13 flows x 64 ch. (unchanged)
// ---------------------------------------------------------------------------
__global__ void warp_k(int t, const float* __restrict__ outp)
{
    int pix = blockIdx.x * 256 + threadIdx.x;
    int l   = blockIdx.y;
    int b   = blockIdx.z;

    float u = g_fl[(b * 26 + 2 * l + 0) * NPIX + pix];
    float v = g_fl[(b * 26 + 2 * l + 1) * NPIX + pix];
    float sx = (float)(pix & 127) - u;
    float sy = (float)(pix >> 7)  - v;

    float fx = floorf(sx), fy = floorf(sy);
    float wx1 = sx - fx, wx0 = 1.f - wx1;
    float wy1 = sy - fy, wy0 = 1.f - wy1;
    int x0 = (int)fx, y0 = (int)fy;
    int x1 = x0 + 1,  y1 = y0 + 1;

    bool vx0 = (x0 >= 0) & (x0 <= 127);
    bool vx1 = (x1 >= 0) & (x1 <= 127);
    bool vy0 = (y0 >= 0) & (y0 <= 127);
    bool vy1 = (y1 >= 0) & (y1 <= 127);

    int cx0 = min(max(x0, 0), 127), cx1 = min(max(x1, 0), 127);
    int cy0 = min(max(y0, 0), 127), cy1 = min(max(y1, 0), 127);

    int i00 = cy0 * 128 + cx0, i10 = cy0 * 128 + cx1;
    int i01 = cy1 * 128 + cx0, i11 = cy1 * 128 + cx1;

    float w00 = (vx0 && vy0) ? wx0 * wy0 : 0.f;
    float w10 = (vx1 && vy0) ? wx1 * wy0 : 0.f;
    float w01 = (vx0 && vy1) ? wx0 * wy1 : 0.f;
    float w11 = (vx1 && vy1) ? wx1 * wy1 : 0.f;

    const float* hp = outp + ((b * 6 + (t - 1)) * 64) * NPIX;
    float* wp = g_wp + ((b * 13 + l) * 64) * NPIX + pix;

    #pragma unroll 4
    for (int c = 0; c < 64; c++) {
        const float* hc = hp + c * NPIX;
        float val = w00 * __ldg(&hc[i00]) + w10 * __ldg(&hc[i10])
                  + w01 * __ldg(&hc[i01]) + w11 * __ldg(&hc[i11]);
        wp[c * NPIX] = val;
    }
}

// ---------------------------------------------------------------------------
// ret: C[192,16384] = W[192,832] * X[832,16384] + bias, per batch.
// TF32 tensor cores with 3xTF32 split (hi/lo) for fp32-grade accuracy.
// BM=96, BN=128, BK=16. 256 threads = 8 warps (2m x 4n), warp tile 48x32.
// grid (128, 2, 2).
// ---------------------------------------------------------------------------
__global__ __launch_bounds__(256, 2) void ret_k(const float* __restrict__ W,
                                                const float* __restrict__ bias, int first)
{
    // pads chosen so row-stride % 32 == 8 -> frag loads hit 32 distinct banks
    __shared__ float As_hi[16][104], As_lo[16][104];
    __shared__ float Bs_hi[16][136], Bs_lo[16][136];

    int tid = threadIdx.x;
    int lane = tid & 31;
    int g  = lane >> 2;          // groupID 0..7
    int t4 = lane & 3;           // threadInGroup 0..3
    int wid = tid >> 5;
    int wm = wid >> 2;           // 0..1
    int wn = wid & 3;            // 0..3
    int mb = wm * 48;
    int nb = wn * 32;

    int b  = blockIdx.z;
    int n0 = blockIdx.x * 128;
    int m0 = blockIdx.y * 96;
    const float* X = g_wp + b * 832 * NPIX;

    float acc[3][4][4];
    #pragma unroll
    for (int mt = 0; mt < 3; mt++)
        #pragma unroll
        for (int nt = 0; nt < 4; nt++)
            #pragma unroll
            for (int i = 0; i < 4; i++) acc[mt][nt][i] = 0.f;

    int nk = first ? 0 : 52;
    for (int kt = 0; kt < nk; kt++) {
        int k0 = kt * 16;
        __syncthreads();   // previous iter's compute done before overwrite

        // ---- A tile: 96 x 16 fp32 -> hi/lo, stored transposed [k][m] ----
        {
            int f = tid;                   // 384 float4 tasks; threads<128 do 2
            #pragma unroll
            for (int r = 0; r < 2; r++) {
                if (f < 384) {
                    int m = f >> 2, kq = (f & 3) * 4;
                    float4 wv = *(const float4*)&W[(m0 + m) * 832 + k0 + kq];
                    float vv[4] = {wv.x, wv.y, wv.z, wv.w};
                    #pragma unroll
                    for (int i = 0; i < 4; i++) {
                        uint32_t hi = f2tf32(vv[i]);
                        uint32_t lo = f2tf32(vv[i] - __uint_as_float(hi));
                        As_hi[kq + i][m] = __uint_as_float(hi);
                        As_lo[kq + i][m] = __uint_as_float(lo);
                    }
                }
                f += 256;
            }
        }
        // ---- B tile: 16 x 128 fp32 -> hi/lo, [k][n] ----
        {
            #pragma unroll
            for (int r = 0; r < 2; r++) {
                int f = tid + r * 256;     // 512 float4 tasks
                int kb = f >> 5, nq = (f & 31) * 4;
                float4 xv = *(const float4*)&X[(k0 + kb) * NPIX + n0 + nq];
                float vv[4] = {xv.x, xv.y, xv.z, xv.w};
                float hi4[4], lo4[4];
                #pragma unroll
                for (int i = 0; i < 4; i++) {
                    uint32_t hi = f2tf32(vv[i]);
                    uint32_t lo = f2tf32(vv[i] - __uint_as_float(hi));
                    hi4[i] = __uint_as_float(hi);
                    lo4[i] = __uint_as_float(lo);
                }
                *(float4*)&Bs_hi[kb][nq] = *(float4*)hi4;
                *(float4*)&Bs_lo[kb][nq] = *(float4*)lo4;
            }
        }
        __syncthreads();

        // ---- compute: 2 k-steps of 8 ----
        #pragma unroll
        for (int kk = 0; kk < 2; kk++) {
            int kr = kk * 8 + t4;
            uint32_t ah[3][4], al[3][4], bh[4][2], bl[4][2];
            #pragma unroll
            for (int mt = 0; mt < 3; mt++) {
                int mm = mb + mt * 16 + g;
                ah[mt][0] = __float_as_uint(As_hi[kr    ][mm    ]);
                ah[mt][1] = __float_as_uint(As_hi[kr    ][mm + 8]);
                ah[mt][2] = __float_as_uint(As_hi[kr + 4][mm    ]);
                ah[mt][3] = __float_as_uint(As_hi[kr + 4][mm + 8]);
                al[mt][0] = __float_as_uint(As_lo[kr    ][mm    ]);
                al[mt][1] = __float_as_uint(As_lo[kr    ][mm + 8]);
                al[mt][2] = __float_as_uint(As_lo[kr + 4][mm    ]);
                al[mt][3] = __float_as_uint(As_lo[kr + 4][mm + 8]);
            }
            #pragma unroll
            for (int nt = 0; nt < 4; nt++) {
                int nn = nb + nt * 8 + g;
                bh[nt][0] = __float_as_uint(Bs_hi[kr    ][nn]);
                bh[nt][1] = __float_as_uint(Bs_hi[kr + 4][nn]);
                bl[nt][0] = __float_as_uint(Bs_lo[kr    ][nn]);
                bl[nt][1] = __float_as_uint(Bs_lo[kr + 4][nn]);
            }
            #pragma unroll
            for (int mt = 0; mt < 3; mt++)
                #pragma unroll
                for (int nt = 0; nt < 4; nt++) {
                    float* c = acc[mt][nt];
                    MMA_TF32(c[0], c[1], c[2], c[3],
                             al[mt][0], al[mt][1], al[mt][2], al[mt][3],
                             bh[nt][0], bh[nt][1]);
                    MMA_TF32(c[0], c[1], c[2], c[3],
                             ah[mt][0], ah[mt][1], ah[mt][2], ah[mt][3],
                             bl[nt][0], bl[nt][1]);
                    MMA_TF32(c[0], c[1], c[2], c[3],
                             ah[mt][0], ah[mt][1], ah[mt][2], ah[mt][3],
                             bh[nt][0], bh[nt][1]);
                }
        }
    }

    // ---- epilogue: add bias, store ----
    float* C = g_h2h + b * 192 * NPIX;
    #pragma unroll
    for (int mt = 0; mt < 3; mt++) {
        int m = m0 + mb + mt * 16 + g;
        float bb0 = bias[m], bb1 = bias[m + 8];
        #pragma unroll
        for (int nt = 0; nt < 4; nt++) {
            int col = n0 + nb + nt * 8 + t4 * 2;
            float2 o0 = make_float2(acc[mt][nt][0] + bb0, acc[mt][nt][1] + bb0);
            float2 o1 = make_float2(acc[mt][nt][2] + bb1, acc[mt][nt][3] + bb1);
            *(float2*)&C[m * NPIX + col]       = o0;
            *(float2*)&C[(m + 8) * NPIX + col] = o1;
        }
    }
}

// ---------------------------------------------------------------------------
// GRU elementwise update; writes out[b, t].
// ---------------------------------------------------------------------------
__global__ void gru_k(int t, int first, float* __restrict__ outp)
{
    int pix = blockIdx.x * 256 + threadIdx.x;
    int c   = blockIdx.y;
    int b   = blockIdx.z;
    int base = b * 192 * NPIX;

    float ir = g_i2h[base + (c      ) * NPIX + pix];
    float iu = g_i2h[base + (c +  64) * NPIX + pix];
    float im = g_i2h[base + (c + 128) * NPIX + pix];
    float hr = g_h2h[base + (c      ) * NPIX + pix];
    float hu = g_h2h[base + (c +  64) * NPIX + pix];
    float hm = g_h2h[base + (c + 128) * NPIX + pix];

    float r = 1.f / (1.f + expf(-(ir + hr)));
    float z = 1.f / (1.f + expf(-(iu + hu)));
    float m = leaky_f(im + r * hm);

    float hp = first ? 0.f : outp[((b * 6 + t - 1) * 64 + c) * NPIX + pix];
    outp[((b * 6 + t) * 64 + c) * NPIX + pix] = z * hp + (1.f - z) * m;
}

// ---------------------------------------------------------------------------
// Launch
// ---------------------------------------------------------------------------
extern "C" void kernel_launch(void* const* d_in, const int* in_sizes, int n_in,
                              void* d_out, int out_size)
{
    const float* x      = (const float*)d_in[0];
    const float* w_stem = (const float*)d_in[1];
    const float* b_stem = (const float*)d_in[2];
    const float* w_i2h  = (const float*)d_in[3];
    const float* b_i2h  = (const float*)d_in[4];
    const float* w_i2f  = (const float*)d_in[5];
    const float* b_i2f  = (const float*)d_in[6];
    const float* w_h2f  = (const float*)d_in[7];
    const float* b_h2f  = (const float*)d_in[8];
    const float* w_flow = (const float*)d_in[9];
    const float* b_flow = (const float*)d_in[10];
    const float* w_ret  = (const float*)d_in[11];
    const float* b_ret  = (const float*)d_in[12];
    float* outp = (float*)d_out;

    stem_k<<<dim3(64, 96, 2), 256>>>(x, w_stem, b_stem);

    for (int t = 0; t < 6; t++) {
        int first = (t == 0) ? 1 : 0;
        i2h_k   <<<dim3(8, 24, 2), 256>>>(t, w_i2h, b_i2h);
        f1_k    <<<dim3(8, 16, 2), 256>>>(t, first, w_i2f, w_h2f, outp);
        f1comb_k<<<(2 * 32 * NPIX) / 256, 256>>>(b_i2f, b_h2f, first);
        flow_k  <<<dim3(8, 8, 2), 256>>>(w_flow);
        flowcomb_k<<<(2 * 26 * NPIX + 255) / 256, 256>>>(b_flow);
        if (!first)
            warp_k<<<dim3(64, 13, 2), 256>>>(t, outp);
        ret_k   <<<dim3(128, 2, 2), 256>>>(w_ret, b_ret, first);
        gru_k   <<<dim3(64, 64, 2), 256>>>(t, first, outp);
    }
}

// round 6
// speedup vs baseline: 1.1699x; 1.0481x over previous
#include <cuda_runtime.h>
#include <math.h>
#include <stdint.h>

#define NPIX 16384            // 128*128
#define H2 128
#define W2 128

// ---------------------------------------------------------------------------
// Scratch (static device globals)
// ---------------------------------------------------------------------------
__device__ float g_ys [2 * 384 * NPIX];     // stem output               50 MB
__device__ float g_i2h[2 * 192 * NPIX];     // i2h conv out              25 MB
__device__ float g_h2h[2 * 192 * NPIX];     // ret conv out              25 MB
__device__ float g_f1 [2 *  32 * NPIX];     // combined flow features     4 MB
__device__ float g_f1p[2][2 * 32 * NPIX];   // f1 partial sums (2 src)  8.4 MB
__device__ float g_fl [2 *  26 * NPIX];     // flows                    3.4 MB
__device__ float g_flp[2][2 * 32 * NPIX];   // flow partial sums        8.4 MB
__device__ float g_wp [2 * 832 * NPIX];     // warped hidden            109 MB

__device__ __forceinline__ float leaky_f(float x) { return x >= 0.f ? x : 0.2f * x; }

__device__ __forceinline__ uint32_t f2tf32(float x) {
    uint32_t r;
    asm("cvt.rna.tf32.f32 %0, %1;" : "=r"(r) : "f"(x));
    return r;
}

#define MMA_TF32(c0,c1,c2,c3, a0,a1,a2,a3, b0,b1)                              \
    asm volatile("mma.sync.aligned.m16n8k8.row.col.f32.tf32.tf32.f32 "         \
        "{%0,%1,%2,%3}, {%4,%5,%6,%7}, {%8,%9}, {%0,%1,%2,%3};"                \
        : "+f"(c0), "+f"(c1), "+f"(c2), "+f"(c3)                               \
        : "r"(a0), "r"(a1), "r"(a2), "r"(a3), "r"(b0), "r"(b1))

// ---------------------------------------------------------------------------
// Stem: conv 3x3 stride 2 pad 1, (B,6,256,256) -> (B,384,128,128), leaky
// ---------------------------------------------------------------------------
__global__ void stem_k(const float* __restrict__ x, const float* __restrict__ w,
                       const float* __restrict__ bias)
{
    int pix = blockIdx.x * 256 + threadIdx.x;
    int oc0 = blockIdx.y * 4;
    int b   = blockIdx.z;
    int oy = pix >> 7, ox = pix & 127;

    float a0 = bias[oc0 + 0], a1 = bias[oc0 + 1], a2 = bias[oc0 + 2], a3 = bias[oc0 + 3];

    #pragma unroll
    for (int ic = 0; ic < 6; ic++) {
        const float* xb = x + (b * 6 + ic) * 65536;
        #pragma unroll
        for (int ky = 0; ky < 3; ky++) {
            int iy = 2 * oy - 1 + ky;
            if (iy < 0 || iy > 255) continue;
            #pragma unroll
            for (int kx = 0; kx < 3; kx++) {
                int ix = 2 * ox - 1 + kx;
                if (ix < 0 || ix > 255) continue;
                float v = __ldg(&xb[iy * 256 + ix]);
                int wi = ic * 9 + ky * 3 + kx;
                a0 += v * __ldg(&w[(oc0 + 0) * 54 + wi]);
                a1 += v * __ldg(&w[(oc0 + 1) * 54 + wi]);
                a2 += v * __ldg(&w[(oc0 + 2) * 54 + wi]);
                a3 += v * __ldg(&w[(oc0 + 3) * 54 + wi]);
            }
        }
    }
    g_ys[(b * 384 + oc0 + 0) * NPIX + pix] = leaky_f(a0);
    g_ys[(b * 384 + oc0 + 1) * NPIX + pix] = leaky_f(a1);
    g_ys[(b * 384 + oc0 + 2) * NPIX + pix] = leaky_f(a2);
    g_ys[(b * 384 + oc0 + 3) * NPIX + pix] = leaky_f(a3);
}

// ---------------------------------------------------------------------------
// i2h via TF32 tensor cores (3xTF32 split), implicit GEMM over 9 taps.
// BM=64 oc, BN=256 px (2 rows x 128). 8 warps: 2m x 4n (warp 32oc x 64px).
// smem: weights [9][8 ic][72] hi/lo, input [8 ic][4 rows][136] hi/lo (dyn).
// grid (64, 3, 2), block 256.
// ---------------------------------------------------------------------------
#define I2H_SMEM_FLOATS (2 * (9 * 8 * 72) + 2 * (8 * 552))
__global__ __launch_bounds__(256) void i2h_k(int t, const float* __restrict__ w,
                                             const float* __restrict__ bias)
{
    extern __shared__ float smem_dyn[];
    float* s_wh = smem_dyn;                    // 9*8*72 = 5184
    float* s_wl = s_wh + 9 * 8 * 72;
    float* s_xh = s_wl + 9 * 8 * 72;           // 8*552  = 4416 (4 rows x 136 + pad8)
    float* s_xl = s_xh + 8 * 552;

    int tid = threadIdx.x;
    int lane = tid & 31;
    int g  = lane >> 2;
    int t4 = lane & 3;
    int wid = tid >> 5;
    int wm = wid >> 2;                         // 0..1
    int wn = wid & 3;                          // 0..3
    int ry = wn >> 1;                          // warp's output row within tile
    int xoff = (wn & 1) * 64;                  // warp's x offset

    int y0 = blockIdx.x * 2;
    int m0 = blockIdx.y * 64;
    int b  = blockIdx.z;
    const float* in = g_ys + (b * 384 + t * 64) * NPIX;

    float acc[2][8][4];
    #pragma unroll
    for (int mt = 0; mt < 2; mt++)
        #pragma unroll
        for (int nt = 0; nt < 8; nt++)
            #pragma unroll
            for (int i = 0; i < 4; i++) acc[mt][nt][i] = 0.f;

    for (int c0 = 0; c0 < 64; c0 += 8) {
        __syncthreads();
        // weights chunk: 64 oc x 8 ic x 9 taps -> [tap][ic][oc(72 pad)]
        for (int i = tid; i < 4608; i += 256) {
            int oc = i / 72, r = i % 72, ic = r / 9, tap = r % 9;
            float v = w[((m0 + oc) * 64 + c0 + ic) * 9 + tap];
            uint32_t hi = f2tf32(v);
            s_wh[(tap * 8 + ic) * 72 + oc] = __uint_as_float(hi);
            s_wl[(tap * 8 + ic) * 72 + oc] = __uint_as_float(f2tf32(v - __uint_as_float(hi)));
        }
        // input chunk: 8 ic x 4 rows x 130 cols (halo +-1)
        for (int i = tid; i < 4160; i += 256) {
            int ic = i / 520, r = i % 520, row = r / 130, col = r % 130;
            int gy = y0 - 1 + row, gx = col - 1;
            float v = 0.f;
            if (gy >= 0 && gy < 128 && gx >= 0 && gx < 128)
                v = in[(c0 + ic) * NPIX + gy * 128 + gx];
            uint32_t hi = f2tf32(v);
            s_xh[ic * 552 + row * 136 + col] = __uint_as_float(hi);
            s_xl[ic * 552 + row * 136 + col] = __uint_as_float(f2tf32(v - __uint_as_float(hi)));
        }
        __syncthreads();

        #pragma unroll 1
        for (int ky = 0; ky < 3; ky++) {
            #pragma unroll
            for (int kx = 0; kx < 3; kx++) {
                int tap = ky * 3 + kx;
                const float* Ah = &s_wh[tap * 8 * 72];
                const float* Al = &s_wl[tap * 8 * 72];
                uint32_t ah[2][4], al[2][4];
                #pragma unroll
                for (int mt = 0; mt < 2; mt++) {
                    int mm = wm * 32 + mt * 16 + g;
                    ah[mt][0] = __float_as_uint(Ah[(t4    ) * 72 + mm    ]);
                    ah[mt][1] = __float_as_uint(Ah[(t4    ) * 72 + mm + 8]);
                    ah[mt][2] = __float_as_uint(Ah[(t4 + 4) * 72 + mm    ]);
                    ah[mt][3] = __float_as_uint(Ah[(t4 + 4) * 72 + mm + 8]);
                    al[mt][0] = __float_as_uint(Al[(t4    ) * 72 + mm    ]);
                    al[mt][1] = __float_as_uint(Al[(t4    ) * 72 + mm + 8]);
                    al[mt][2] = __float_as_uint(Al[(t4 + 4) * 72 + mm    ]);
                    al[mt][3] = __float_as_uint(Al[(t4 + 4) * 72 + mm + 8]);
                }
                int base = (ry + ky) * 136 + xoff + kx;
                const float* Xh = &s_xh[base];
                const float* Xl = &s_xl[base];
                #pragma unroll
                for (int nt = 0; nt < 8; nt++) {
                    int cc = nt * 8 + g;
                    uint32_t bh0 = __float_as_uint(Xh[(t4    ) * 552 + cc]);
                    uint32_t bh1 = __float_as_uint(Xh[(t4 + 4) * 552 + cc]);
                    uint32_t bl0 = __float_as_uint(Xl[(t4    ) * 552 + cc]);
                    uint32_t bl1 = __float_as_uint(Xl[(t4 + 4) * 552 + cc]);
                    #pragma unroll
                    for (int mt = 0; mt < 2; mt++) {
                        float* c = acc[mt][nt];
                        MMA_TF32(c[0], c[1], c[2], c[3],
                                 al[mt][0], al[mt][1], al[mt][2], al[mt][3], bh0, bh1);
                        MMA_TF32(c[0], c[1], c[2], c[3],
                                 ah[mt][0], ah[mt][1], ah[mt][2], ah[mt][3], bl0, bl1);
                        MMA_TF32(c[0], c[1], c[2], c[3],
                                 ah[mt][0], ah[mt][1], ah[mt][2], ah[mt][3], bh0, bh1);
                    }
                }
            }
        }
    }

    int pix0 = (y0 + ry) * 128 + xoff;
    #pragma unroll
    for (int mt = 0; mt < 2; mt++) {
        int m = m0 + wm * 32 + mt * 16 + g;
        float bb0 = bias[m], bb1 = bias[m + 8];
        float* C0 = &g_i2h[(b * 192 + m    ) * NPIX];
        float* C1 = &g_i2h[(b * 192 + m + 8) * NPIX];
        #pragma unroll
        for (int nt = 0; nt < 8; nt++) {
            int px = pix0 + nt * 8 + t4 * 2;
            *(float2*)&C0[px] = make_float2(acc[mt][nt][0] + bb0, acc[mt][nt][1] + bb0);
            *(float2*)&C1[px] = make_float2(acc[mt][nt][2] + bb1, acc[mt][nt][3] + bb1);
        }
    }
}

// ---------------------------------------------------------------------------
// f1 via TF32 tensor cores: conv5x5 of one source (xt or hprev) -> partial.
// BM=32 oc, BN=128 px (1 row). 8 warps each: 2 m-tiles x 16 px.
// smem: weights [25][8][40] hi/lo, input [8][5 rows][136] hi/lo (dyn).
// grid (128, 2 src, 2 b), block 256. t=0: src1 returns (partial unused).
// ---------------------------------------------------------------------------
#define F1_SMEM_FLOATS (2 * (25 * 8 * 40) + 2 * (8 * 680))
__global__ __launch_bounds__(256) void f1_k(int t, int first,
                                            const float* __restrict__ wi,
                                            const float* __restrict__ wh,
                                            const float* __restrict__ outp)
{
    int src = blockIdx.y;
    if (first && src) return;

    extern __shared__ float smem_dyn[];
    float* s_wh = smem_dyn;                    // 25*8*40 = 8000
    float* s_wl = s_wh + 25 * 8 * 40;
    float* s_xh = s_wl + 25 * 8 * 40;          // 8*680 (5 rows x 136)
    float* s_xl = s_xh + 8 * 680;

    int tid = threadIdx.x;
    int lane = tid & 31;
    int g  = lane >> 2;
    int t4 = lane & 3;
    int wid = tid >> 5;

    int y0 = blockIdx.x;
    int b  = blockIdx.z;

    const float* in = src ? (outp + ((b * 6 + (t - 1)) * 64) * NPIX)
                          : (g_ys + (b * 384 + t * 64) * NPIX);
    const float* w  = src ? wh : wi;

    float acc[2][2][4];
    #pragma unroll
    for (int mt = 0; mt < 2; mt++)
        #pragma unroll
        for (int nt = 0; nt < 2; nt++)
            #pragma unroll
            for (int i = 0; i < 4; i++) acc[mt][nt][i] = 0.f;

    for (int c0 = 0; c0 < 64; c0 += 8) {
        __syncthreads();
        // weights chunk: 32 oc x 8 ic x 25 taps -> [tap][ic][oc(40 pad)]
        for (int i = tid; i < 6400; i += 256) {
            int oc = i / 200, r = i % 200, ic = r / 25, tap = r % 25;
            float v = w[(oc * 64 + c0 + ic) * 25 + tap];
            uint32_t hi = f2tf32(v);
            s_wh[(tap * 8 + ic) * 40 + oc] = __uint_as_float(hi);
            s_wl[(tap * 8 + ic) * 40 + oc] = __uint_as_float(f2tf32(v - __uint_as_float(hi)));
        }
        // input chunk: 8 ic x 5 rows x 132 cols (halo +-2)
        for (int i = tid; i < 5280; i += 256) {
            int ic = i / 660, r = i % 660, row = r / 132, col = r % 132;
            int gy = y0 - 2 + row, gx = col - 2;
            float v = 0.f;
            if (gy >= 0 && gy < 128 && gx >= 0 && gx < 128)
                v = in[(c0 + ic) * NPIX + gy * 128 + gx];
            uint32_t hi = f2tf32(v);
            s_xh[ic * 680 + row * 136 + col] = __uint_as_float(hi);
            s_xl[ic * 680 + row * 136 + col] = __uint_as_float(f2tf32(v - __uint_as_float(hi)));
        }
        __syncthreads();

        #pragma unroll 1
        for (int ky = 0; ky < 5; ky++) {
            #pragma unroll
            for (int kx = 0; kx < 5; kx++) {
                int tap = ky * 5 + kx;
                const float* Ah = &s_wh[tap * 8 * 40];
                const float* Al = &s_wl[tap * 8 * 40];
                uint32_t ah[2][4], al[2][4];
                #pragma unroll
                for (int mt = 0; mt < 2; mt++) {
                    int mm = mt * 16 + g;
                    ah[mt][0] = __float_as_uint(Ah[(t4    ) * 40 + mm    ]);
                    ah[mt][1] = __float_as_uint(Ah[(t4    ) * 40 + mm + 8]);
                    ah[mt][2] = __float_as_uint(Ah[(t4 + 4) * 40 + mm    ]);
                    ah[mt][3] = __float_as_uint(Ah[(t4 + 4) * 40 + mm + 8]);
                    al[mt][0] = __float_as_uint(Al[(t4    ) * 40 + mm    ]);
                    al[mt][1] = __float_as_uint(Al[(t4    ) * 40 + mm + 8]);
                    al[mt][2] = __float_as_uint(Al[(t4 + 4) * 40 + mm    ]);
                    al[mt][3] = __float_as_uint(Al[(t4 + 4) * 40 + mm + 8]);
                }
                int base = ky * 136 + wid * 16 + kx;
                const float* Xh = &s_xh[base];
                const float* Xl = &s_xl[base];
                #pragma unroll
                for (int nt = 0; nt < 2; nt++) {
                    int cc = nt * 8 + g;
                    uint32_t bh0 = __float_as_uint(Xh[(t4    ) * 680 + cc]);
                    uint32_t bh1 = __float_as_uint(Xh[(t4 + 4) * 680 + cc]);
                    uint32_t bl0 = __float_as_uint(Xl[(t4    ) * 680 + cc]);
                    uint32_t bl1 = __float_as_uint(Xl[(t4 + 4) * 680 + cc]);
                    #pragma unroll
                    for (int mt = 0; mt < 2; mt++) {
                        float* c = acc[mt][nt];
                        MMA_TF32(c[0], c[1], c[2], c[3],
                                 al[mt][0], al[mt][1], al[mt][2], al[mt][3], bh0, bh1);
                        MMA_TF32(c[0], c[1], c[2], c[3],
                                 ah[mt][0], ah[mt][1], ah[mt][2], ah[mt][3], bl0, bl1);
                        MMA_TF32(c[0], c[1], c[2], c[3],
                                 ah[mt][0], ah[mt][1], ah[mt][2], ah[mt][3], bh0, bh1);
                    }
                }
            }
        }
    }

    float* op = g_f1p[src];
    #pragma unroll
    for (int mt = 0; mt < 2; mt++) {
        int m = mt * 16 + g;
        float* C0 = &op[(b * 32 + m    ) * NPIX];
        float* C1 = &op[(b * 32 + m + 8) * NPIX];
        #pragma unroll
        for (int nt = 0; nt < 2; nt++) {
            int px = y0 * 128 + wid * 16 + nt * 8 + t4 * 2;
            *(float2*)&C0[px] = make_float2(acc[mt][nt][0], acc[mt][nt][1]);
            *(float2*)&C1[px] = make_float2(acc[mt][nt][2], acc[mt][nt][3]);
        }
    }
}

// f1 combine: sum src partials + both biases, leaky -> g_f1
__global__ void f1comb_k(const float* __restrict__ bi, const float* __restrict__ bh, int first)
{
    int idx = blockIdx.x * 256 + threadIdx.x;
    int c = (idx >> 14) & 31;
    float v = g_f1p[0][idx];
    if (!first) v += g_f1p[1][idx];
    v += bi[c] + bh[c];
    g_f1[idx] = leaky_f(v);
}

// ---------------------------------------------------------------------------
// flow: conv 5x5 pad 2, 32 -> 26 (padded to 32 oc), FFMA path (small).
// ---------------------------------------------------------------------------
__global__ __launch_bounds__(256) void flow_k(const float* __restrict__ w)
{
    __shared__ __align__(16) float s_in[4][68][40];
    __shared__ __align__(16) float s_w [4][25][8];

    int csplit = blockIdx.y >> 2;
    int oc0    = (blockIdx.y & 3) * 8;
    int cbase  = csplit * 16;

    int tid = threadIdx.x;
    int tx = tid & 3, ty = tid >> 2;
    int xt0 = (blockIdx.x & 3) * 32;
    int yt0 = (blockIdx.x >> 2) * 64;
    int b   = blockIdx.z;
    const float* in = g_f1 + (b * 32 + cbase) * NPIX;

    float acc[8][8];
    #pragma unroll
    for (int j = 0; j < 8; j++)
        #pragma unroll
        for (int p = 0; p < 8; p++) acc[j][p] = 0.f;

    for (int c0 = 0; c0 < 16; c0 += 4) {
        for (int i = tid; i < 800; i += 256) {
            int ic = i / 200, r = i % 200, k = r >> 3, j = r & 7;
            s_w[ic][k][j] = (oc0 + j < 26)
                ? w[((oc0 + j) * 32 + cbase + c0 + ic) * 25 + k] : 0.f;
        }
        for (int i = tid; i < 4 * 68 * 40; i += 256) {
            int ic = i / 2720, r = i % 2720, ly = r / 40, lx = r % 40;
            int gy = yt0 + ly - 2, gx = xt0 + lx - 2;
            float v = 0.f;
            if (lx < 36 && gy >= 0 && gy < 128 && gx >= 0 && gx < 128)
                v = in[(c0 + ic) * NPIX + gy * 128 + gx];
            s_in[ic][ly][lx] = v;
        }
        __syncthreads();

        #pragma unroll 1
        for (int ic = 0; ic < 4; ic++) {
            #pragma unroll 1
            for (int ky = 0; ky < 5; ky++) {
                float bb[12];
                *(float4*)&bb[0] = *(const float4*)&s_in[ic][ty + ky][tx * 8];
                *(float4*)&bb[4] = *(const float4*)&s_in[ic][ty + ky][tx * 8 + 4];
                *(float4*)&bb[8] = *(const float4*)&s_in[ic][ty + ky][tx * 8 + 8];
                #pragma unroll
                for (int kx = 0; kx < 5; kx++) {
                    float a[8];
                    *(float4*)&a[0] = *(const float4*)&s_w[ic][ky * 5 + kx][0];
                    *(float4*)&a[4] = *(const float4*)&s_w[ic][ky * 5 + kx][4];
                    #pragma unroll
                    for (int j = 0; j < 8; j++)
                        #pragma unroll
                        for (int p = 0; p < 8; p++)
                            acc[j][p] += a[j] * bb[kx + p];
                }
            }
        }
        __syncthreads();
    }

    int pix = (yt0 + ty) * 128 + xt0 + tx * 8;
    float* op = g_flp[csplit];
    #pragma unroll
    for (int j = 0; j < 8; j++) {
        float* o = &op[(b * 32 + oc0 + j) * NPIX + pix];
        *(float4*)&o[0] = *(float4*)&acc[j][0];
        *(float4*)&o[4] = *(float4*)&acc[j][4];
    }
}

__global__ void flowcomb_k(const float* __restrict__ bias)
{
    int idx = blockIdx.x * 256 + threadIdx.x;
    if (idx >= 2 * 26 * NPIX) return;
    int b = idx / (26 * NPIX);
    int r = idx - b * (26 * NPIX);
    int c = r >> 14;
    int pix = r & (NPIX - 1);
    int pi = (b * 32 + c) * NPIX + pix;
    g_fl[idx] = g_flp[0][pi] + g_flp[1][pi] + bias[c];
}

// ---------------------------------------------------------------------------
// warp: bilinear sample hprev at (x-u, y-v), 13 flows x 64 ch.
// ---------------------------------------------------------------------------
__global__ void warp_k(int t, const float* __restrict__ outp)
{
    int pix = blockIdx.x * 256 + threadIdx.x;
    int l   = blockIdx.y;
    int b   = blockIdx.z;

    float u = g_fl[(b * 26 + 2 * l + 0) * NPIX + pix];
    float v = g_fl[(b * 26 + 2 * l + 1) * NPIX + pix];
    float sx = (float)(pix & 127) - u;
    float sy = (float)(pix >> 7)  - v;

    float fx = floorf(sx), fy = floorf(sy);
    float wx1 = sx - fx, wx0 = 1.f - wx1;
    float wy1 = sy - fy, wy0 = 1.f - wy1;
    int x0 = (int)fx, y0 = (int)fy;
    int x1 = x0 + 1,  y1 = y0 + 1;

    bool vx0 = (x0 >= 0) & (x0 <= 127);
    bool vx1 = (x1 >= 0) & (x1 <= 127);
    bool vy0 = (y0 >= 0) & (y0 <= 127);
    bool vy1 = (y1 >= 0) & (y1 <= 127);

    int cx0 = min(max(x0, 0), 127), cx1 = min(max(x1, 0), 127);
    int cy0 = min(max(y0, 0), 127), cy1 = min(max(y1, 0), 127);

    int i00 = cy0 * 128 + cx0, i10 = cy0 * 128 + cx1;
    int i01 = cy1 * 128 + cx0, i11 = cy1 * 128 + cx1;

    float w00 = (vx0 && vy0) ? wx0 * wy0 : 0.f;
    float w10 = (vx1 && vy0) ? wx1 * wy0 : 0.f;
    float w01 = (vx0 && vy1) ? wx0 * wy1 : 0.f;
    float w11 = (vx1 && vy1) ? wx1 * wy1 : 0.f;

    const float* hp = outp + ((b * 6 + (t - 1)) * 64) * NPIX;
    float* wp = g_wp + ((b * 13 + l) * 64) * NPIX + pix;

    #pragma unroll 4
    for (int c = 0; c < 64; c++) {
        const float* hc = hp + c * NPIX;
        float val = w00 * __ldg(&hc[i00]) + w10 * __ldg(&hc[i10])
                  + w01 * __ldg(&hc[i01]) + w11 * __ldg(&hc[i11]);
        wp[c * NPIX] = val;
    }
}

// ---------------------------------------------------------------------------
// ret: C[192,16384] = W[192,832] * X[832,16384] + bias, per batch.
// TF32 tensor cores with 3xTF32 split. BM=96, BN=128, BK=16. grid (128,2,2).
// ---------------------------------------------------------------------------
__global__ __launch_bounds__(256, 2) void ret_k(const float* __restrict__ W,
                                                const float* __restrict__ bias, int first)
{
    __shared__ float As_hi[16][104], As_lo[16][104];
    __shared__ float Bs_hi[16][136], Bs_lo[16][136];

    int tid = threadIdx.x;
    int lane = tid & 31;
    int g  = lane >> 2;
    int t4 = lane & 3;
    int wid = tid >> 5;
    int wm = wid >> 2;
    int wn = wid & 3;
    int mb = wm * 48;
    int nb = wn * 32;

    int b  = blockIdx.z;
    int n0 = blockIdx.x * 128;
    int m0 = blockIdx.y * 96;
    const float* X = g_wp + b * 832 * NPIX;

    float acc[3][4][4];
    #pragma unroll
    for (int mt = 0; mt < 3; mt++)
        #pragma unroll
        for (int nt = 0; nt < 4; nt++)
            #pragma unroll
            for (int i = 0; i < 4; i++) acc[mt][nt][i] = 0.f;

    int nk = first ? 0 : 52;
    for (int kt = 0; kt < nk; kt++) {
        int k0 = kt * 16;
        __syncthreads();

        {
            int f = tid;
            #pragma unroll
            for (int r = 0; r < 2; r++) {
                if (f < 384) {
                    int m = f >> 2, kq = (f & 3) * 4;
                    float4 wv = *(const float4*)&W[(m0 + m) * 832 + k0 + kq];
                    float vv[4] = {wv.x, wv.y, wv.z, wv.w};
                    #pragma unroll
                    for (int i = 0; i < 4; i++) {
                        uint32_t hi = f2tf32(vv[i]);
                        uint32_t lo = f2tf32(vv[i] - __uint_as_float(hi));
                        As_hi[kq + i][m] = __uint_as_float(hi);
                        As_lo[kq + i][m] = __uint_as_float(lo);
                    }
                }
                f += 256;
            }
        }
        {
            #pragma unroll
            for (int r = 0; r < 2; r++) {
                int f = tid + r * 256;
                int kb = f >> 5, nq = (f & 31) * 4;
                float4 xv = *(const float4*)&X[(k0 + kb) * NPIX + n0 + nq];
                float vv[4] = {xv.x, xv.y, xv.z, xv.w};
                float hi4[4], lo4[4];
                #pragma unroll
                for (int i = 0; i < 4; i++) {
                    uint32_t hi = f2tf32(vv[i]);
                    uint32_t lo = f2tf32(vv[i] - __uint_as_float(hi));
                    hi4[i] = __uint_as_float(hi);
                    lo4[i] = __uint_as_float(lo);
                }
                *(float4*)&Bs_hi[kb][nq] = *(float4*)hi4;
                *(float4*)&Bs_lo[kb][nq] = *(float4*)lo4;
            }
        }
        __syncthreads();

        #pragma unroll
        for (int kk = 0; kk < 2; kk++) {
            int kr = kk * 8 + t4;
            uint32_t ah[3][4], al[3][4], bh[4][2], bl[4][2];
            #pragma unroll
            for (int mt = 0; mt < 3; mt++) {
                int mm = mb + mt * 16 + g;
                ah[mt][0] = __float_as_uint(As_hi[kr    ][mm    ]);
                ah[mt][1] = __float_as_uint(As_hi[kr    ][mm + 8]);
                ah[mt][2] = __float_as_uint(As_hi[kr + 4][mm    ]);
                ah[mt][3] = __float_as_uint(As_hi[kr + 4][mm + 8]);
                al[mt][0] = __float_as_uint(As_lo[kr    ][mm    ]);
                al[mt][1] = __float_as_uint(As_lo[kr    ][mm + 8]);
                al[mt][2] = __float_as_uint(As_lo[kr + 4][mm    ]);
                al[mt][3] = __float_as_uint(As_lo[kr + 4][mm + 8]);
            }
            #pragma unroll
            for (int nt = 0; nt < 4; nt++) {
                int nn = nb + nt * 8 + g;
                bh[nt][0] = __float_as_uint(Bs_hi[kr    ][nn]);
                bh[nt][1] = __float_as_uint(Bs_hi[kr + 4][nn]);
                bl[nt][0] = __float_as_uint(Bs_lo[kr    ][nn]);
                bl[nt][1] = __float_as_uint(Bs_lo[kr + 4][nn]);
            }
            #pragma unroll
            for (int mt = 0; mt < 3; mt++)
                #pragma unroll
                for (int nt = 0; nt < 4; nt++) {
                    float* c = acc[mt][nt];
                    MMA_TF32(c[0], c[1], c[2], c[3],
                             al[mt][0], al[mt][1], al[mt][2], al[mt][3],
                             bh[nt][0], bh[nt][1]);
                    MMA_TF32(c[0], c[1], c[2], c[3],
                             ah[mt][0], ah[mt][1], ah[mt][2], ah[mt][3],
                             bl[nt][0], bl[nt][1]);
                    MMA_TF32(c[0], c[1], c[2], c[3],
                             ah[mt][0], ah[mt][1], ah[mt][2], ah[mt][3],
                             bh[nt][0], bh[nt][1]);
                }
        }
    }

    float* C = g_h2h + b * 192 * NPIX;
    #pragma unroll
    for (int mt = 0; mt < 3; mt++) {
        int m = m0 + mb + mt * 16 + g;
        float bb0 = bias[m], bb1 = bias[m + 8];
        #pragma unroll
        for (int nt = 0; nt < 4; nt++) {
            int col = n0 + nb + nt * 8 + t4 * 2;
            float2 o0 = make_float2(acc[mt][nt][0] + bb0, acc[mt][nt][1] + bb0);
            float2 o1 = make_float2(acc[mt][nt][2] + bb1, acc[mt][nt][3] + bb1);
            *(float2*)&C[m * NPIX + col]       = o0;
            *(float2*)&C[(m + 8) * NPIX + col] = o1;
        }
    }
}

// ---------------------------------------------------------------------------
// GRU elementwise update; writes out[b, t].
// ---------------------------------------------------------------------------
__global__ void gru_k(int t, int first, float* __restrict__ outp)
{
    int pix = blockIdx.x * 256 + threadIdx.x;
    int c   = blockIdx.y;
    int b   = blockIdx.z;
    int base = b * 192 * NPIX;

    float ir = g_i2h[base + (c      ) * NPIX + pix];
    float iu = g_i2h[base + (c +  64) * NPIX + pix];
    float im = g_i2h[base + (c + 128) * NPIX + pix];
    float hr = g_h2h[base + (c      ) * NPIX + pix];
    float hu = g_h2h[base + (c +  64) * NPIX + pix];
    float hm = g_h2h[base + (c + 128) * NPIX + pix];

    float r = 1.f / (1.f + expf(-(ir + hr)));
    float z = 1.f / (1.f + expf(-(iu + hu)));
    float m = leaky_f(im + r * hm);

    float hp = first ? 0.f : outp[((b * 6 + t - 1) * 64 + c) * NPIX + pix];
    outp[((b * 6 + t) * 64 + c) * NPIX + pix] = z * hp + (1.f - z) * m;
}

// ---------------------------------------------------------------------------
// Launch
// ---------------------------------------------------------------------------
extern "C" void kernel_launch(void* const* d_in, const int* in_sizes, int n_in,
                              void* d_out, int out_size)
{
    const float* x      = (const float*)d_in[0];
    const float* w_stem = (const float*)d_in[1];
    const float* b_stem = (const float*)d_in[2];
    const float* w_i2h  = (const float*)d_in[3];
    const float* b_i2h  = (const float*)d_in[4];
    const float* w_i2f  = (const float*)d_in[5];
    const float* b_i2f  = (const float*)d_in[6];
    const float* w_h2f  = (const float*)d_in[7];
    const float* b_h2f  = (const float*)d_in[8];
    const float* w_flow = (const float*)d_in[9];
    const float* b_flow = (const float*)d_in[10];
    const float* w_ret  = (const float*)d_in[11];
    const float* b_ret  = (const float*)d_in[12];
    float* outp = (float*)d_out;

    const int I2H_SMEM = I2H_SMEM_FLOATS * 4;   // 76800 B
    const int F1_SMEM  = F1_SMEM_FLOATS * 4;    // 107520 B
    cudaFuncSetAttribute(i2h_k, cudaFuncAttributeMaxDynamicSharedMemorySize, I2H_SMEM);
    cudaFuncSetAttribute(f1_k,  cudaFuncAttributeMaxDynamicSharedMemorySize, F1_SMEM);

    stem_k<<<dim3(64, 96, 2), 256>>>(x, w_stem, b_stem);

    for (int t = 0; t < 6; t++) {
        int first = (t == 0) ? 1 : 0;
        i2h_k   <<<dim3(64, 3, 2), 256, I2H_SMEM>>>(t, w_i2h, b_i2h);
        f1_k    <<<dim3(128, 2, 2), 256, F1_SMEM>>>(t, first, w_i2f, w_h2f, outp);
        f1comb_k<<<(2 * 32 * NPIX) / 256, 256>>>(b_i2f, b_h2f, first);
        flow_k  <<<dim3(8, 8, 2), 256>>>(w_flow);
        flowcomb_k<<<(2 * 26 * NPIX + 255) / 256, 256>>>(b_flow);
        if (!first)
            warp_k<<<dim3(64, 13, 2), 256>>>(t, outp);
        ret_k   <<<dim3(128, 2, 2), 256>>>(w_ret, b_ret, first);
        gru_k   <<<dim3(64, 64, 2), 256>>>(t, first, outp);
    }
}

// round 7
// speedup vs baseline: 1.8137x; 1.5502x over previous
#include <cuda_runtime.h>
#include <cuda_bf16.h>
#include <math.h>
#include <stdint.h>

#define NPIX 16384            // 128*128

// ---------------------------------------------------------------------------
// Scratch (static device globals)
// ---------------------------------------------------------------------------
__device__ float g_i2h[2 * 192 * NPIX];     // i2h conv out              25 MB
__device__ float g_h2h[2 * 192 * NPIX];     // ret conv out              25 MB
__device__ float g_f1p[2][2 * 32 * NPIX];   // f1 partial sums (2 src)  8.4 MB
__device__ float g_fl [2 *  26 * NPIX];     // flows                    3.4 MB
__device__ float g_wp [2 * 832 * NPIX];     // warped hidden            109 MB

// bf16-split packed operands (ic-pairs per 32-bit word)
__device__ uint32_t g_ysbf_h[2 * 192 * NPIX], g_ysbf_l[2 * 192 * NPIX]; // stem out
__device__ uint32_t g_hbf_h [2 *  32 * NPIX], g_hbf_l [2 *  32 * NPIX]; // hprev
__device__ uint32_t g_f1bf_h[2 *  16 * NPIX], g_f1bf_l[2 *  16 * NPIX]; // f1 out

// pre-converted weights: layouts match smem consumption order
__device__ uint32_t g_wi2h_h[3 * 4 * 9 * 8 * 64],  g_wi2h_l[3 * 4 * 9 * 8 * 64];
__device__ uint32_t g_wf1_h [2 * 4 * 25 * 8 * 32], g_wf1_l [2 * 4 * 25 * 8 * 32];
__device__ uint32_t g_wfl_h [2 * 25 * 8 * 32],     g_wfl_l [2 * 25 * 8 * 32];

__device__ __forceinline__ float leaky_f(float x) { return x >= 0.f ? x : 0.2f * x; }

__device__ __forceinline__ uint32_t f2tf32(float x) {
    uint32_t r;
    asm("cvt.rna.tf32.f32 %0, %1;" : "=r"(r) : "f"(x));
    return r;
}

// split two floats into packed bf16 hi-pair and lo-pair (v = hi + lo)
__device__ __forceinline__ void split2(float v0, float v1, uint32_t& h, uint32_t& l) {
    __nv_bfloat162 hb = __floats2bfloat162_rn(v0, v1);
    float h0 = __low2float(hb), h1 = __high2float(hb);
    __nv_bfloat162 lb = __floats2bfloat162_rn(v0 - h0, v1 - h1);
    h = *reinterpret_cast<uint32_t*>(&hb);
    l = *reinterpret_cast<uint32_t*>(&lb);
}

#define MMA_TF32(c0,c1,c2,c3, a0,a1,a2,a3, b0,b1)                              \
    asm volatile("mma.sync.aligned.m16n8k8.row.col.f32.tf32.tf32.f32 "         \
        "{%0,%1,%2,%3}, {%4,%5,%6,%7}, {%8,%9}, {%0,%1,%2,%3};"                \
        : "+f"(c0), "+f"(c1), "+f"(c2), "+f"(c3)                               \
        : "r"(a0), "r"(a1), "r"(a2), "r"(a3), "r"(b0), "r"(b1))

#define MMA_BF16(c0,c1,c2,c3, a0,a1,a2,a3, b0,b1)                              \
    asm volatile("mma.sync.aligned.m16n8k16.row.col.f32.bf16.bf16.f32 "        \
        "{%0,%1,%2,%3}, {%4,%5,%6,%7}, {%8,%9}, {%0,%1,%2,%3};"                \
        : "+f"(c0), "+f"(c1), "+f"(c2), "+f"(c3)                               \
        : "r"(a0), "r"(a1), "r"(a2), "r"(a3), "r"(b0), "r"(b1))

// ---------------------------------------------------------------------------
// Weight prep (run once per launch; weights are t-invariant)
// ---------------------------------------------------------------------------
// i2h: [ocg3][chunk4][tap9][kp8][oc64]
__global__ void wprep_i2h_k(const float* __restrict__ w)
{
    int idx = blockIdx.x * 256 + threadIdx.x;
    if (idx >= 55296) return;
    int oc = idx & 63;
    int kp = (idx >> 6) & 7;
    int q  = idx >> 9;
    int tap = q % 9;
    int qc  = q / 9;
    int chunk = qc & 3, ocg = qc >> 2;
    int ic = chunk * 16 + 2 * kp;
    int o  = ocg * 64 + oc;
    float v0 = w[(o * 64 + ic    ) * 9 + tap];
    float v1 = w[(o * 64 + ic + 1) * 9 + tap];
    split2(v0, v1, g_wi2h_h[idx], g_wi2h_l[idx]);
}

// f1: [src2][chunk4][tap25][kp8][oc32]
__global__ void wprep_f1_k(const float* __restrict__ wi, const float* __restrict__ wh)
{
    int idx = blockIdx.x * 256 + threadIdx.x;
    if (idx >= 51200) return;
    int oc = idx & 31;
    int kp = (idx >> 5) & 7;
    int q  = idx >> 8;
    int tap = q % 25;
    int qc  = q / 25;
    int chunk = qc & 3, src = qc >> 2;
    int ic = chunk * 16 + 2 * kp;
    const float* w = src ? wh : wi;
    float v0 = w[(oc * 64 + ic    ) * 25 + tap];
    float v1 = w[(oc * 64 + ic + 1) * 25 + tap];
    split2(v0, v1, g_wf1_h[idx], g_wf1_l[idx]);
}

// flow: [chunk2][tap25][kp8][oc32] (oc >= 26 zero-padded)
__global__ void wprep_fl_k(const float* __restrict__ w)
{
    int idx = blockIdx.x * 256 + threadIdx.x;
    if (idx >= 12800) return;
    int oc = idx & 31;
    int kp = (idx >> 5) & 7;
    int q  = idx >> 8;
    int tap = q % 25;
    int chunk = q / 25;
    int ic = chunk * 16 + 2 * kp;
    float v0 = 0.f, v1 = 0.f;
    if (oc < 26) {
        v0 = w[(oc * 32 + ic    ) * 25 + tap];
        v1 = w[(oc * 32 + ic + 1) * 25 + tap];
    }
    split2(v0, v1, g_wfl_h[idx], g_wfl_l[idx]);
}

// ---------------------------------------------------------------------------
// Stem: conv 3x3 stride 2 pad 1, (B,6,256,256) -> bf16-split (B,384,128,128)
// ---------------------------------------------------------------------------
__global__ void stem_k(const float* __restrict__ x, const float* __restrict__ w,
                       const float* __restrict__ bias)
{
    int pix = blockIdx.x * 256 + threadIdx.x;
    int oc0 = blockIdx.y * 4;
    int b   = blockIdx.z;
    int oy = pix >> 7, ox = pix & 127;

    float a0 = bias[oc0 + 0], a1 = bias[oc0 + 1], a2 = bias[oc0 + 2], a3 = bias[oc0 + 3];

    #pragma unroll
    for (int ic = 0; ic < 6; ic++) {
        const float* xb = x + (b * 6 + ic) * 65536;
        #pragma unroll
        for (int ky = 0; ky < 3; ky++) {
            int iy = 2 * oy - 1 + ky;
            if (iy < 0 || iy > 255) continue;
            #pragma unroll
            for (int kx = 0; kx < 3; kx++) {
                int ix = 2 * ox - 1 + kx;
                if (ix < 0 || ix > 255) continue;
                float v = __ldg(&xb[iy * 256 + ix]);
                int wi = ic * 9 + ky * 3 + kx;
                a0 += v * __ldg(&w[(oc0 + 0) * 54 + wi]);
                a1 += v * __ldg(&w[(oc0 + 1) * 54 + wi]);
                a2 += v * __ldg(&w[(oc0 + 2) * 54 + wi]);
                a3 += v * __ldg(&w[(oc0 + 3) * 54 + wi]);
            }
        }
    }
    a0 = leaky_f(a0); a1 = leaky_f(a1); a2 = leaky_f(a2); a3 = leaky_f(a3);
    uint32_t h0, l0, h1, l1;
    split2(a0, a1, h0, l0);
    split2(a2, a3, h1, l1);
    int p = ((b * 384 + oc0) >> 1) * NPIX + pix;
    g_ysbf_h[p] = h0;        g_ysbf_l[p] = l0;
    g_ysbf_h[p + NPIX] = h1; g_ysbf_l[p + NPIX] = l1;
}

// ---------------------------------------------------------------------------
// i2h: conv3x3 64->192 via bf16-split mma.m16n8k16.
// BM=64 oc, BN=256 px (2 rows). 8 warps = 2m x 4n; warp = 32oc x 64px.
// grid (64, 3, 2), block 256, smem 76.8KB (2 blocks/SM).
// ---------------------------------------------------------------------------
#define I2H_SMEM_BYTES ((2 * 5184 + 2 * 4416) * 4)
__global__ __launch_bounds__(256) void i2h_k(int t, const float* __restrict__ bias)
{
    extern __shared__ uint32_t sm_u[];
    uint32_t* s_wh = sm_u;                 // [tap*8+kp][72]  5184
    uint32_t* s_wl = s_wh + 5184;
    uint32_t* s_xh = s_wl + 5184;          // kp stride 552, row stride 136
    uint32_t* s_xl = s_xh + 4416;

    int tid = threadIdx.x;
    int lane = tid & 31;
    int g  = lane >> 2;
    int t4 = lane & 3;
    int wid = tid >> 5;
    int wm = wid >> 2;
    int wn = wid & 3;
    int ry = wn >> 1;
    int xoff = (wn & 1) * 64;

    int y0 = blockIdx.x * 2;
    int ocg = blockIdx.y;
    int m0 = ocg * 64;
    int b  = blockIdx.z;
    const uint32_t* inh = g_ysbf_h + (b * 192 + t * 32) * NPIX;
    const uint32_t* inl = g_ysbf_l + (b * 192 + t * 32) * NPIX;

    float acc[2][8][4];
    #pragma unroll
    for (int mt = 0; mt < 2; mt++)
        #pragma unroll
        for (int nt = 0; nt < 8; nt++)
            #pragma unroll
            for (int i = 0; i < 4; i++) acc[mt][nt][i] = 0.f;

    for (int chunk = 0; chunk < 4; chunk++) {
        __syncthreads();
        int wbase = (ocg * 4 + chunk) * 4608;
        for (int i = tid; i < 4608; i += 256) {
            int smi = (i >> 6) * 72 + (i & 63);
            s_wh[smi] = g_wi2h_h[wbase + i];
            s_wl[smi] = g_wi2h_l[wbase + i];
        }
        int pbase = chunk * 8;            // pair-plane offset (c0/2)
        for (int i = tid; i < 4160; i += 256) {
            int col = i % 130, r = i / 130;
            int row = r & 3, kp = r >> 2;
            int gy = y0 - 1 + row, gx = col - 1;
            uint32_t vh = 0, vl = 0;
            if (gy >= 0 && gy < 128 && gx >= 0 && gx < 128) {
                int off = (pbase + kp) * NPIX + gy * 128 + gx;
                vh = inh[off]; vl = inl[off];
            }
            int si = kp * 552 + row * 136 + col;
            s_xh[si] = vh; s_xl[si] = vl;
        }
        __syncthreads();

        #pragma unroll
        for (int ky = 0; ky < 3; ky++) {
            #pragma unroll
            for (int kx = 0; kx < 3; kx++) {
                int tap = ky * 3 + kx;
                uint32_t ah[2][4], al[2][4];
                #pragma unroll
                for (int mt = 0; mt < 2; mt++) {
                    int mm = wm * 32 + mt * 16 + g;
                    int r0 = (tap * 8 + t4) * 72, r1 = (tap * 8 + t4 + 4) * 72;
                    ah[mt][0] = s_wh[r0 + mm];     ah[mt][1] = s_wh[r0 + mm + 8];
                    ah[mt][2] = s_wh[r1 + mm];     ah[mt][3] = s_wh[r1 + mm + 8];
                    al[mt][0] = s_wl[r0 + mm];     al[mt][1] = s_wl[r0 + mm + 8];
                    al[mt][2] = s_wl[r1 + mm];     al[mt][3] = s_wl[r1 + mm + 8];
                }
                int base = (ry + ky) * 136 + xoff + kx;
                #pragma unroll
                for (int nt = 0; nt < 8; nt++) {
                    int cc = base + nt * 8 + g;
                    uint32_t bh0 = s_xh[t4 * 552 + cc];
                    uint32_t bh1 = s_xh[(t4 + 4) * 552 + cc];
                    uint32_t bl0 = s_xl[t4 * 552 + cc];
                    uint32_t bl1 = s_xl[(t4 + 4) * 552 + cc];
                    #pragma unroll
                    for (int mt = 0; mt < 2; mt++) {
                        float* c = acc[mt][nt];
                        MMA_BF16(c[0], c[1], c[2], c[3],
                                 al[mt][0], al[mt][1], al[mt][2], al[mt][3], bh0, bh1);
                        MMA_BF16(c[0], c[1], c[2], c[3],
                                 ah[mt][0], ah[mt][1], ah[mt][2], ah[mt][3], bl0, bl1);
                        MMA_BF16(c[0], c[1], c[2], c[3],
                                 ah[mt][0], ah[mt][1], ah[mt][2], ah[mt][3], bh0, bh1);
                    }
                }
            }
        }
    }

    int pix0 = (y0 + ry) * 128 + xoff;
    #pragma unroll
    for (int mt = 0; mt < 2; mt++) {
        int m = m0 + wm * 32 + mt * 16 + g;
        float bb0 = bias[m], bb1 = bias[m + 8];
        float* C0 = &g_i2h[(b * 192 + m    ) * NPIX];
        float* C1 = &g_i2h[(b * 192 + m + 8) * NPIX];
        #pragma unroll
        for (int nt = 0; nt < 8; nt++) {
            int px = pix0 + nt * 8 + t4 * 2;
            *(float2*)&C0[px] = make_float2(acc[mt][nt][0] + bb0, acc[mt][nt][1] + bb0);
            *(float2*)&C1[px] = make_float2(acc[mt][nt][2] + bb1, acc[mt][nt][3] + bb1);
        }
    }
}

// ---------------------------------------------------------------------------
// f1: conv5x5 of one source (64 ic -> 32 oc), bf16-split TC, partial sums.
// BM=32 oc, BN=512 px (4 rows). 8 warps = 4row x 2half; warp = 32oc x 64px.
// grid (32, 2 src, 2 b), block 256, smem 134KB (1 block/SM).
// ---------------------------------------------------------------------------
#define C5_SMEM_BYTES ((2 * 8000 + 2 * 8768) * 4)
__global__ __launch_bounds__(256) void f1_k(int t, int first)
{
    int src = blockIdx.y;
    if (first && src) return;

    extern __shared__ uint32_t sm_u[];
    uint32_t* s_wh = sm_u;                 // [tap*8+kp][40]  8000
    uint32_t* s_wl = s_wh + 8000;
    uint32_t* s_xh = s_wl + 8000;          // kp stride 1096, row stride 136
    uint32_t* s_xl = s_xh + 8768;

    int tid = threadIdx.x;
    int lane = tid & 31;
    int g  = lane >> 2;
    int t4 = lane & 3;
    int wid = tid >> 5;
    int rw = wid >> 1;
    int xoff = (wid & 1) * 64;

    int y0 = blockIdx.x * 4;
    int b  = blockIdx.z;
    const uint32_t* inh = src ? (g_hbf_h + b * 32 * NPIX) : (g_ysbf_h + (b * 192 + t * 32) * NPIX);
    const uint32_t* inl = src ? (g_hbf_l + b * 32 * NPIX) : (g_ysbf_l + (b * 192 + t * 32) * NPIX);

    float acc[2][8][4];
    #pragma unroll
    for (int mt = 0; mt < 2; mt++)
        #pragma unroll
        for (int nt = 0; nt < 8; nt++)
            #pragma unroll
            for (int i = 0; i < 4; i++) acc[mt][nt][i] = 0.f;

    for (int chunk = 0; chunk < 4; chunk++) {
        __syncthreads();
        int wbase = (src * 4 + chunk) * 6400;
        for (int i = tid; i < 6400; i += 256) {
            int smi = (i >> 5) * 40 + (i & 31);
            s_wh[smi] = g_wf1_h[wbase + i];
            s_wl[smi] = g_wf1_l[wbase + i];
        }
        int pbase = chunk * 8;
        for (int i = tid; i < 8448; i += 256) {
            int col = i % 132, r = i / 132;
            int row = r & 7, kp = r >> 3;
            int gy = y0 - 2 + row, gx = col - 2;
            uint32_t vh = 0, vl = 0;
            if (gy >= 0 && gy < 128 && gx >= 0 && gx < 128) {
                int off = (pbase + kp) * NPIX + gy * 128 + gx;
                vh = inh[off]; vl = inl[off];
            }
            int si = kp * 1096 + row * 136 + col;
            s_xh[si] = vh; s_xl[si] = vl;
        }
        __syncthreads();

        #pragma unroll 1
        for (int ky = 0; ky < 5; ky++) {
            #pragma unroll
            for (int kx = 0; kx < 5; kx++) {
                int tap = ky * 5 + kx;
                uint32_t ah[2][4], al[2][4];
                #pragma unroll
                for (int mt = 0; mt < 2; mt++) {
                    int mm = mt * 16 + g;
                    int r0 = (tap * 8 + t4) * 40, r1 = (tap * 8 + t4 + 4) * 40;
                    ah[mt][0] = s_wh[r0 + mm];     ah[mt][1] = s_wh[r0 + mm + 8];
                    ah[mt][2] = s_wh[r1 + mm];     ah[mt][3] = s_wh[r1 + mm + 8];
                    al[mt][0] = s_wl[r0 + mm];     al[mt][1] = s_wl[r0 + mm + 8];
                    al[mt][2] = s_wl[r1 + mm];     al[mt][3] = s_wl[r1 + mm + 8];
                }
                int base = (rw + ky) * 136 + xoff + kx;
                #pragma unroll
                for (int nt = 0; nt < 8; nt++) {
                    int cc = base + nt * 8 + g;
                    uint32_t bh0 = s_xh[t4 * 1096 + cc];
                    uint32_t bh1 = s_xh[(t4 + 4) * 1096 + cc];
                    uint32_t bl0 = s_xl[t4 * 1096 + cc];
                    uint32_t bl1 = s_xl[(t4 + 4) * 1096 + cc];
                    #pragma unroll
                    for (int mt = 0; mt < 2; mt++) {
                        float* c = acc[mt][nt];
                        MMA_BF16(c[0], c[1], c[2], c[3],
                                 al[mt][0], al[mt][1], al[mt][2], al[mt][3], bh0, bh1);
                        MMA_BF16(c[0], c[1], c[2], c[3],
                                 ah[mt][0], ah[mt][1], ah[mt][2], ah[mt][3], bl0, bl1);
                        MMA_BF16(c[0], c[1], c[2], c[3],
                                 ah[mt][0], ah[mt][1], ah[mt][2], ah[mt][3], bh0, bh1);
                    }
                }
            }
        }
    }

    float* op = g_f1p[src];
    int pix0 = (y0 + rw) * 128 + xoff;
    #pragma unroll
    for (int mt = 0; mt < 2; mt++) {
        int m = mt * 16 + g;
        float* C0 = &op[(b * 32 + m    ) * NPIX];
        float* C1 = &op[(b * 32 + m + 8) * NPIX];
        #pragma unroll
        for (int nt = 0; nt < 8; nt++) {
            int px = pix0 + nt * 8 + t4 * 2;
            *(float2*)&C0[px] = make_float2(acc[mt][nt][0], acc[mt][nt][1]);
            *(float2*)&C1[px] = make_float2(acc[mt][nt][2], acc[mt][nt][3]);
        }
    }
}

// f1 combine: sum src partials + biases, leaky -> bf16-split pairs
__global__ void f1comb_k(const float* __restrict__ bi, const float* __restrict__ bh, int first)
{
    int idx = blockIdx.x * 256 + threadIdx.x;        // 2b x 16 pairs x NPIX
    int pix = idx & (NPIX - 1);
    int c2  = (idx >> 14) & 15;
    int b   = idx >> 18;
    int c   = 2 * c2;
    int p0 = (b * 32 + c) * NPIX + pix;
    float v0 = g_f1p[0][p0];
    float v1 = g_f1p[0][p0 + NPIX];
    if (!first) { v0 += g_f1p[1][p0]; v1 += g_f1p[1][p0 + NPIX]; }
    v0 = leaky_f(v0 + bi[c] + bh[c]);
    v1 = leaky_f(v1 + bi[c + 1] + bh[c + 1]);
    uint32_t h, l;
    split2(v0, v1, h, l);
    g_f1bf_h[idx] = h; g_f1bf_l[idx] = l;
}

// ---------------------------------------------------------------------------
// flow: conv5x5 32 -> 26 (padded 32), bf16-split TC, writes g_fl + bias.
// Same geometry as f1. grid (32, 1, 2).
// ---------------------------------------------------------------------------
__global__ __launch_bounds__(256) void flow_k(const float* __restrict__ bias)
{
    extern __shared__ uint32_t sm_u[];
    uint32_t* s_wh = sm_u;
    uint32_t* s_wl = s_wh + 8000;
    uint32_t* s_xh = s_wl + 8000;
    uint32_t* s_xl = s_xh + 8768;

    int tid = threadIdx.x;
    int lane = tid & 31;
    int g  = lane >> 2;
    int t4 = lane & 3;
    int wid = tid >> 5;
    int rw = wid >> 1;
    int xoff = (wid & 1) * 64;

    int y0 = blockIdx.x * 4;
    int b  = blockIdx.z;
    const uint32_t* inh = g_f1bf_h + b * 16 * NPIX;
    const uint32_t* inl = g_f1bf_l + b * 16 * NPIX;

    float acc[2][8][4];
    #pragma unroll
    for (int mt = 0; mt < 2; mt++)
        #pragma unroll
        for (int nt = 0; nt < 8; nt++)
            #pragma unroll
            for (int i = 0; i < 4; i++) acc[mt][nt][i] = 0.f;

    for (int chunk = 0; chunk < 2; chunk++) {
        __syncthreads();
        int wbase = chunk * 6400;
        for (int i = tid; i < 6400; i += 256) {
            int smi = (i >> 5) * 40 + (i & 31);
            s_wh[smi] = g_wfl_h[wbase + i];
            s_wl[smi] = g_wfl_l[wbase + i];
        }
        int pbase = chunk * 8;
        for (int i = tid; i < 8448; i += 256) {
            int col = i % 132, r = i / 132;
            int row = r & 7, kp = r >> 3;
            int gy = y0 - 2 + row, gx = col - 2;
            uint32_t vh = 0, vl = 0;
            if (gy >= 0 && gy < 128 && gx >= 0 && gx < 128) {
                int off = (pbase + kp) * NPIX + gy * 128 + gx;
                vh = inh[off]; vl = inl[off];
            }
            int si = kp * 1096 + row * 136 + col;
            s_xh[si] = vh; s_xl[si] = vl;
        }
        __syncthreads();

        #pragma unroll 1
        for (int ky = 0; ky < 5; ky++) {
            #pragma unroll
            for (int kx = 0; kx < 5; kx++) {
                int tap = ky * 5 + kx;
                uint32_t ah[2][4], al[2][4];
                #pragma unroll
                for (int mt = 0; mt < 2; mt++) {
                    int mm = mt * 16 + g;
                    int r0 = (tap * 8 + t4) * 40, r1 = (tap * 8 + t4 + 4) * 40;
                    ah[mt][0] = s_wh[r0 + mm];     ah[mt][1] = s_wh[r0 + mm + 8];
                    ah[mt][2] = s_wh[r1 + mm];     ah[mt][3] = s_wh[r1 + mm + 8];
                    al[mt][0] = s_wl[r0 + mm];     al[mt][1] = s_wl[r0 + mm + 8];
                    al[mt][2] = s_wl[r1 + mm];     al[mt][3] = s_wl[r1 + mm + 8];
                }
                int base = (rw + ky) * 136 + xoff + kx;
                #pragma unroll
                for (int nt = 0; nt < 8; nt++) {
                    int cc = base + nt * 8 + g;
                    uint32_t bh0 = s_xh[t4 * 1096 + cc];
                    uint32_t bh1 = s_xh[(t4 + 4) * 1096 + cc];
                    uint32_t bl0 = s_xl[t4 * 1096 + cc];
                    uint32_t bl1 = s_xl[(t4 + 4) * 1096 + cc];
                    #pragma unroll
                    for (int mt = 0; mt < 2; mt++) {
                        float* c = acc[mt][nt];
                        MMA_BF16(c[0], c[1], c[2], c[3],
                                 al[mt][0], al[mt][1], al[mt][2], al[mt][3], bh0, bh1);
                        MMA_BF16(c[0], c[1], c[2], c[3],
                                 ah[mt][0], ah[mt][1], ah[mt][2], ah[mt][3], bl0, bl1);
                        MMA_BF16(c[0], c[1], c[2], c[3],
                                 ah[mt][0], ah[mt][1], ah[mt][2], ah[mt][3], bh0, bh1);
                    }
                }
            }
        }
    }

    int pix0 = (y0 + rw) * 128 + xoff;
    #pragma unroll
    for (int mt = 0; mt < 2; mt++) {
        int m = mt * 16 + g;
        #pragma unroll
        for (int nt = 0; nt < 8; nt++) {
            int px = pix0 + nt * 8 + t4 * 2;
            if (m < 26) {
                float bb = bias[m];
                *(float2*)&g_fl[(b * 26 + m) * NPIX + px] =
                    make_float2(acc[mt][nt][0] + bb, acc[mt][nt][1] + bb);
            }
            if (m + 8 < 26) {
                float bb = bias[m + 8];
                *(float2*)&g_fl[(b * 26 + m + 8) * NPIX + px] =
                    make_float2(acc[mt][nt][2] + bb, acc[mt][nt][3] + bb);
            }
        }
    }
}

// ---------------------------------------------------------------------------
// warp: bilinear sample hprev at (x-u, y-v), 13 flows x 64 ch.
// ---------------------------------------------------------------------------
__global__ void warp_k(int t, const float* __restrict__ outp)
{
    int pix = blockIdx.x * 256 + threadIdx.x;
    int l   = blockIdx.y;
    int b   = blockIdx.z;

    float u = g_fl[(b * 26 + 2 * l + 0) * NPIX + pix];
    float v = g_fl[(b * 26 + 2 * l + 1) * NPIX + pix];
    float sx = (float)(pix & 127) - u;
    float sy = (float)(pix >> 7)  - v;

    float fx = floorf(sx), fy = floorf(sy);
    float wx1 = sx - fx, wx0 = 1.f - wx1;
    float wy1 = sy - fy, wy0 = 1.f - wy1;
    int x0 = (int)fx, y0 = (int)fy;
    int x1 = x0 + 1,  y1 = y0 + 1;

    bool vx0 = (x0 >= 0) & (x0 <= 127);
    bool vx1 = (x1 >= 0) & (x1 <= 127);
    bool vy0 = (y0 >= 0) & (y0 <= 127);
    bool vy1 = (y1 >= 0) & (y1 <= 127);

    int cx0 = min(max(x0, 0), 127), cx1 = min(max(x1, 0), 127);
    int cy0 = min(max(y0, 0), 127), cy1 = min(max(y1, 0), 127);

    int i00 = cy0 * 128 + cx0, i10 = cy0 * 128 + cx1;
    int i01 = cy1 * 128 + cx0, i11 = cy1 * 128 + cx1;

    float w00 = (vx0 && vy0) ? wx0 * wy0 : 0.f;
    float w10 = (vx1 && vy0) ? wx1 * wy0 : 0.f;
    float w01 = (vx0 && vy1) ? wx0 * wy1 : 0.f;
    float w11 = (vx1 && vy1) ? wx1 * wy1 : 0.f;

    const float* hp = outp + ((b * 6 + (t - 1)) * 64) * NPIX;
    float* wp = g_wp + ((b * 13 + l) * 64) * NPIX + pix;

    #pragma unroll 4
    for (int c = 0; c < 64; c++) {
        const float* hc = hp + c * NPIX;
        float val = w00 * __ldg(&hc[i00]) + w10 * __ldg(&hc[i10])
                  + w01 * __ldg(&hc[i01]) + w11 * __ldg(&hc[i11]);
        wp[c * NPIX] = val;
    }
}

// ---------------------------------------------------------------------------
// ret: C[192,16384] = W[192,832] * X[832,16384] + bias, per batch.
// TF32 3x-split tensor cores. BM=96, BN=128, BK=16. grid (128,2,2).
// ---------------------------------------------------------------------------
__global__ __launch_bounds__(256, 2) void ret_k(const float* __restrict__ W,
                                                const float* __restrict__ bias, int first)
{
    __shared__ float As_hi[16][104], As_lo[16][104];
    __shared__ float Bs_hi[16][136], Bs_lo[16][136];

    int tid = threadIdx.x;
    int lane = tid & 31;
    int g  = lane >> 2;
    int t4 = lane & 3;
    int wid = tid >> 5;
    int wm = wid >> 2;
    int wn = wid & 3;
    int mb = wm * 48;
    int nb = wn * 32;

    int b  = blockIdx.z;
    int n0 = blockIdx.x * 128;
    int m0 = blockIdx.y * 96;
    const float* X = g_wp + b * 832 * NPIX;

    float acc[3][4][4];
    #pragma unroll
    for (int mt = 0; mt < 3; mt++)
        #pragma unroll
        for (int nt = 0; nt < 4; nt++)
            #pragma unroll
            for (int i = 0; i < 4; i++) acc[mt][nt][i] = 0.f;

    int nk = first ? 0 : 52;
    for (int kt = 0; kt < nk; kt++) {
        int k0 = kt * 16;
        __syncthreads();

        {
            int f = tid;
            #pragma unroll
            for (int r = 0; r < 2; r++) {
                if (f < 384) {
                    int m = f >> 2, kq = (f & 3) * 4;
                    float4 wv = *(const float4*)&W[(m0 + m) * 832 + k0 + kq];
                    float vv[4] = {wv.x, wv.y, wv.z, wv.w};
                    #pragma unroll
                    for (int i = 0; i < 4; i++) {
                        uint32_t hi = f2tf32(vv[i]);
                        uint32_t lo = f2tf32(vv[i] - __uint_as_float(hi));
                        As_hi[kq + i][m] = __uint_as_float(hi);
                        As_lo[kq + i][m] = __uint_as_float(lo);
                    }
                }
                f += 256;
            }
        }
        {
            #pragma unroll
            for (int r = 0; r < 2; r++) {
                int f = tid + r * 256;
                int kb = f >> 5, nq = (f & 31) * 4;
                float4 xv = *(const float4*)&X[(k0 + kb) * NPIX + n0 + nq];
                float vv[4] = {xv.x, xv.y, xv.z, xv.w};
                float hi4[4], lo4[4];
                #pragma unroll
                for (int i = 0; i < 4; i++) {
                    uint32_t hi = f2tf32(vv[i]);
                    uint32_t lo = f2tf32(vv[i] - __uint_as_float(hi));
                    hi4[i] = __uint_as_float(hi);
                    lo4[i] = __uint_as_float(lo);
                }
                *(float4*)&Bs_hi[kb][nq] = *(float4*)hi4;
                *(float4*)&Bs_lo[kb][nq] = *(float4*)lo4;
            }
        }
        __syncthreads();

        #pragma unroll
        for (int kk = 0; kk < 2; kk++) {
            int kr = kk * 8 + t4;
            uint32_t ah[3][4], al[3][4], bh[4][2], bl[4][2];
            #pragma unroll
            for (int mt = 0; mt < 3; mt++) {
                int mm = mb + mt * 16 + g;
                ah[mt][0] = __float_as_uint(As_hi[kr    ][mm    ]);
                ah[mt][1] = __float_as_uint(As_hi[kr    ][mm + 8]);
                ah[mt][2] = __float_as_uint(As_hi[kr + 4][mm    ]);
                ah[mt][3] = __float_as_uint(As_hi[kr + 4][mm + 8]);
                al[mt][0] = __float_as_uint(As_lo[kr    ][mm    ]);
                al[mt][1] = __float_as_uint(As_lo[kr    ][mm + 8]);
                al[mt][2] = __float_as_uint(As_lo[kr + 4][mm    ]);
                al[mt][3] = __float_as_uint(As_lo[kr + 4][mm + 8]);
            }
            #pragma unroll
            for (int nt = 0; nt < 4; nt++) {
                int nn = nb + nt * 8 + g;
                bh[nt][0] = __float_as_uint(Bs_hi[kr    ][nn]);
                bh[nt][1] = __float_as_uint(Bs_hi[kr + 4][nn]);
                bl[nt][0] = __float_as_uint(Bs_lo[kr    ][nn]);
                bl[nt][1] = __float_as_uint(Bs_lo[kr + 4][nn]);
            }
            #pragma unroll
            for (int mt = 0; mt < 3; mt++)
                #pragma unroll
                for (int nt = 0; nt < 4; nt++) {
                    float* c = acc[mt][nt];
                    MMA_TF32(c[0], c[1], c[2], c[3],
                             al[mt][0], al[mt][1], al[mt][2], al[mt][3],
                             bh[nt][0], bh[nt][1]);
                    MMA_TF32(c[0], c[1], c[2], c[3],
                             ah[mt][0], ah[mt][1], ah[mt][2], ah[mt][3],
                             bl[nt][0], bl[nt][1]);
                    MMA_TF32(c[0], c[1], c[2], c[3],
                             ah[mt][0], ah[mt][1], ah[mt][2], ah[mt][3],
                             bh[nt][0], bh[nt][1]);
                }
        }
    }

    float* C = g_h2h + b * 192 * NPIX;
    #pragma unroll
    for (int mt = 0; mt < 3; mt++) {
        int m = m0 + mb + mt * 16 + g;
        float bb0 = bias[m], bb1 = bias[m + 8];
        #pragma unroll
        for (int nt = 0; nt < 4; nt++) {
            int col = n0 + nb + nt * 8 + t4 * 2;
            float2 o0 = make_float2(acc[mt][nt][0] + bb0, acc[mt][nt][1] + bb0);
            float2 o1 = make_float2(acc[mt][nt][2] + bb1, acc[mt][nt][3] + bb1);
            *(float2*)&C[m * NPIX + col]       = o0;
            *(float2*)&C[(m + 8) * NPIX + col] = o1;
        }
    }
}

// ---------------------------------------------------------------------------
// GRU update: writes out[b,t] fp32 + bf16-split hidden copy (channel pairs).
// grid (64, 32, 2), block 256.
// ---------------------------------------------------------------------------
__global__ void gru_k(int t, int first, float* __restrict__ outp)
{
    int pix = blockIdx.x * 256 + threadIdx.x;
    int c2  = blockIdx.y;
    int b   = blockIdx.z;
    int c   = 2 * c2;
    int base = b * 192 * NPIX;

    float h01[2];
    #pragma unroll
    for (int j = 0; j < 2; j++) {
        int cj = c + j;
        float ir = g_i2h[base + (cj      ) * NPIX + pix];
        float iu = g_i2h[base + (cj +  64) * NPIX + pix];
        float im = g_i2h[base + (cj + 128) * NPIX + pix];
        float hr = g_h2h[base + (cj      ) * NPIX + pix];
        float hu = g_h2h[base + (cj +  64) * NPIX + pix];
        float hm = g_h2h[base + (cj + 128) * NPIX + pix];

        float r = 1.f / (1.f + expf(-(ir + hr)));
        float z = 1.f / (1.f + expf(-(iu + hu)));
        float m = leaky_f(im + r * hm);

        float hp = first ? 0.f : outp[((b * 6 + t - 1) * 64 + cj) * NPIX + pix];
        float h  = z * hp + (1.f - z) * m;
        outp[((b * 6 + t) * 64 + cj) * NPIX + pix] = h;
        h01[j] = h;
    }
    uint32_t hw, lw;
    split2(h01[0], h01[1], hw, lw);
    int p = (b * 32 + c2) * NPIX + pix;
    g_hbf_h[p] = hw; g_hbf_l[p] = lw;
}

// ---------------------------------------------------------------------------
// Launch
// ---------------------------------------------------------------------------
extern "C" void kernel_launch(void* const* d_in, const int* in_sizes, int n_in,
                              void* d_out, int out_size)
{
    const float* x      = (const float*)d_in[0];
    const float* w_stem = (const float*)d_in[1];
    const float* b_stem = (const float*)d_in[2];
    const float* w_i2h  = (const float*)d_in[3];
    const float* b_i2h  = (const float*)d_in[4];
    const float* w_i2f  = (const float*)d_in[5];
    const float* b_i2f  = (const float*)d_in[6];
    const float* w_h2f  = (const float*)d_in[7];
    const float* b_h2f  = (const float*)d_in[8];
    const float* w_flow = (const float*)d_in[9];
    const float* b_flow = (const float*)d_in[10];
    const float* w_ret  = (const float*)d_in[11];
    const float* b_ret  = (const float*)d_in[12];
    float* outp = (float*)d_out;

    cudaFuncSetAttribute(i2h_k,  cudaFuncAttributeMaxDynamicSharedMemorySize, I2H_SMEM_BYTES);
    cudaFuncSetAttribute(f1_k,   cudaFuncAttributeMaxDynamicSharedMemorySize, C5_SMEM_BYTES);
    cudaFuncSetAttribute(flow_k, cudaFuncAttributeMaxDynamicSharedMemorySize, C5_SMEM_BYTES);

    wprep_i2h_k<<<(55296 + 255) / 256, 256>>>(w_i2h);
    wprep_f1_k <<<(51200 + 255) / 256, 256>>>(w_i2f, w_h2f);
    wprep_fl_k <<<(12800 + 255) / 256, 256>>>(w_flow);

    stem_k<<<dim3(64, 96, 2), 256>>>(x, w_stem, b_stem);

    for (int t = 0; t < 6; t++) {
        int first = (t == 0) ? 1 : 0;
        i2h_k   <<<dim3(64, 3, 2), 256, I2H_SMEM_BYTES>>>(t, b_i2h);
        f1_k    <<<dim3(32, 2, 2), 256, C5_SMEM_BYTES>>>(t, first);
        f1comb_k<<<(2 * 16 * NPIX) / 256, 256>>>(b_i2f, b_h2f, first);
        flow_k  <<<dim3(32, 1, 2), 256, C5_SMEM_BYTES>>>(b_flow);
        if (!first)
            warp_k<<<dim3(64, 13, 2), 256>>>(t, outp);
        ret_k   <<<dim3(128, 2, 2), 256>>>(w_ret, b_ret, first);
        gru_k   <<<dim3(64, 32, 2), 256>>>(t, first, outp);
    }
}

// round 9
// speedup vs baseline: 1.9144x; 1.0555x over previous
#include <cuda_runtime.h>
#include <cuda_bf16.h>
#include <math.h>
#include <stdint.h>

#define NPIX 16384            // 128*128

// ---------------------------------------------------------------------------
// Scratch (static device globals)
// ---------------------------------------------------------------------------
__device__ float g_i2h[2 * 192 * NPIX];     // i2h conv out              25 MB
__device__ float g_h2h[2 * 192 * NPIX];     // ret conv out              25 MB
__device__ float g_f1p[2][2 * 32 * NPIX];   // f1 partial sums (2 src)  8.4 MB
__device__ float g_fl [2 *  26 * NPIX];     // flows                    3.4 MB

// bf16-split packed operands (ic-pairs per 32-bit word)
__device__ uint32_t g_ysbf_h[2 * 192 * NPIX], g_ysbf_l[2 * 192 * NPIX]; // stem out
__device__ uint32_t g_hbf_h [2 *  32 * NPIX], g_hbf_l [2 *  32 * NPIX]; // hprev
__device__ uint32_t g_f1bf_h[2 *  16 * NPIX], g_f1bf_l[2 *  16 * NPIX]; // f1 out

// pre-converted weights: layouts match smem consumption order
__device__ uint32_t g_wi2h_h[3 * 4 * 9 * 8 * 64],  g_wi2h_l[3 * 4 * 9 * 8 * 64];
__device__ uint32_t g_wf1_h [2 * 4 * 25 * 8 * 32], g_wf1_l [2 * 4 * 25 * 8 * 32];
__device__ uint32_t g_wfl_h [2 * 25 * 8 * 32],     g_wfl_l [2 * 25 * 8 * 32];
__device__ uint32_t g_wret_h[2 * 13 * 4 * 8 * 96], g_wret_l[2 * 13 * 4 * 8 * 96];

__device__ __forceinline__ float leaky_f(float x) { return x >= 0.f ? x : 0.2f * x; }

// split two floats into packed bf16 hi-pair and lo-pair (v = hi + lo)
__device__ __forceinline__ void split2(float v0, float v1, uint32_t& h, uint32_t& l) {
    __nv_bfloat162 hb = __floats2bfloat162_rn(v0, v1);
    float h0 = __low2float(hb), h1 = __high2float(hb);
    __nv_bfloat162 lb = __floats2bfloat162_rn(v0 - h0, v1 - h1);
    h = *reinterpret_cast<uint32_t*>(&hb);
    l = *reinterpret_cast<uint32_t*>(&lb);
}

#define MMA_BF16(c0,c1,c2,c3, a0,a1,a2,a3, b0,b1)                              \
    asm volatile("mma.sync.aligned.m16n8k16.row.col.f32.bf16.bf16.f32 "        \
        "{%0,%1,%2,%3}, {%4,%5,%6,%7}, {%8,%9}, {%0,%1,%2,%3};"                \
        : "+f"(c0), "+f"(c1), "+f"(c2), "+f"(c3)                               \
        : "r"(a0), "r"(a1), "r"(a2), "r"(a3), "r"(b0), "r"(b1))

// ---------------------------------------------------------------------------
// Weight prep (run once per launch; weights are t-invariant)
// ---------------------------------------------------------------------------
// i2h: [ocg3][chunk4][tap9][kp8][oc64]
__global__ void wprep_i2h_k(const float* __restrict__ w)
{
    int idx = blockIdx.x * 256 + threadIdx.x;
    if (idx >= 55296) return;
    int oc = idx & 63;
    int kp = (idx >> 6) & 7;
    int q  = idx >> 9;
    int tap = q % 9;
    int qc  = q / 9;
    int chunk = qc & 3, ocg = qc >> 2;
    int ic = chunk * 16 + 2 * kp;
    int o  = ocg * 64 + oc;
    float v0 = w[(o * 64 + ic    ) * 9 + tap];
    float v1 = w[(o * 64 + ic + 1) * 9 + tap];
    split2(v0, v1, g_wi2h_h[idx], g_wi2h_l[idx]);
}

// f1: [src2][chunk4][tap25][kp8][oc32]
__global__ void wprep_f1_k(const float* __restrict__ wi, const float* __restrict__ wh)
{
    int idx = blockIdx.x * 256 + threadIdx.x;
    if (idx >= 51200) return;
    int oc = idx & 31;
    int kp = (idx >> 5) & 7;
    int q  = idx >> 8;
    int tap = q % 25;
    int qc  = q / 25;
    int chunk = qc & 3, src = qc >> 2;
    int ic = chunk * 16 + 2 * kp;
    const float* w = src ? wh : wi;
    float v0 = w[(oc * 64 + ic    ) * 25 + tap];
    float v1 = w[(oc * 64 + ic + 1) * 25 + tap];
    split2(v0, v1, g_wf1_h[idx], g_wf1_l[idx]);
}

// flow: [chunk2][tap25][kp8][oc32] (oc >= 26 zero-padded)
__global__ void wprep_fl_k(const float* __restrict__ w)
{
    int idx = blockIdx.x * 256 + threadIdx.x;
    if (idx >= 12800) return;
    int oc = idx & 31;
    int kp = (idx >> 5) & 7;
    int q  = idx >> 8;
    int tap = q % 25;
    int chunk = q / 25;
    int ic = chunk * 16 + 2 * kp;
    float v0 = 0.f, v1 = 0.f;
    if (oc < 26) {
        v0 = w[(oc * 32 + ic    ) * 25 + tap];
        v1 = w[(oc * 32 + ic + 1) * 25 + tap];
    }
    split2(v0, v1, g_wfl_h[idx], g_wfl_l[idx]);
}

// ret: [mb2][l13][chunk4][kp8][m96]
__global__ void wprep_ret_k(const float* __restrict__ w)
{
    int idx = blockIdx.x * 256 + threadIdx.x;
    if (idx >= 79872) return;
    int m  = idx % 96;
    int kp = (idx / 96) & 7;
    int chunk = (idx / 768) & 3;
    int l  = (idx / 3072) % 13;
    int mb = idx / 39936;
    int k  = l * 64 + chunk * 16 + kp * 2;
    float v0 = w[(mb * 96 + m) * 832 + k];
    float v1 = w[(mb * 96 + m) * 832 + k + 1];
    split2(v0, v1, g_wret_h[idx], g_wret_l[idx]);
}

// ---------------------------------------------------------------------------
// Stem: conv 3x3 stride 2 pad 1, (B,6,256,256) -> bf16-split (B,384,128,128)
// 8 oc/thread, weights staged in smem [tap][oc8]. grid (64, 48, 2).
// ---------------------------------------------------------------------------
__global__ __launch_bounds__(256) void stem_k(const float* __restrict__ x,
                                              const float* __restrict__ w,
                                              const float* __restrict__ bias)
{
    __shared__ __align__(16) float sw[54][8];

    int tid = threadIdx.x;
    int oc0 = blockIdx.y * 8;
    int b   = blockIdx.z;

    for (int i = tid; i < 432; i += 256) {
        int oc = i & 7, tap = i >> 3;
        sw[tap][oc] = w[(oc0 + oc) * 54 + tap];
    }
    __syncthreads();

    int pix = blockIdx.x * 256 + tid;
    int oy = pix >> 7, ox = pix & 127;

    float acc[8];
    #pragma unroll
    for (int j = 0; j < 8; j++) acc[j] = bias[oc0 + j];

    #pragma unroll
    for (int ic = 0; ic < 6; ic++) {
        const float* xb = x + (b * 6 + ic) * 65536;
        float in[9];
        #pragma unroll
        for (int ky = 0; ky < 3; ky++) {
            int iy = 2 * oy - 1 + ky;
            #pragma unroll
            for (int kx = 0; kx < 3; kx++) {
                int ix = 2 * ox - 1 + kx;
                bool ok = (iy >= 0) & (iy <= 255) & (ix >= 0) & (ix <= 255);
                in[ky * 3 + kx] = ok ? __ldg(&xb[iy * 256 + ix]) : 0.f;
            }
        }
        #pragma unroll
        for (int k = 0; k < 9; k++) {
            int tap = ic * 9 + k;
            float a[8];
            *(float4*)&a[0] = *(const float4*)&sw[tap][0];
            *(float4*)&a[4] = *(const float4*)&sw[tap][4];
            #pragma unroll
            for (int j = 0; j < 8; j++) acc[j] += in[k] * a[j];
        }
    }
    #pragma unroll
    for (int j = 0; j < 8; j++) acc[j] = leaky_f(acc[j]);

    int pbase = ((b * 384 + oc0) >> 1) * NPIX + pix;
    #pragma unroll
    for (int j = 0; j < 4; j++) {
        uint32_t h, l;
        split2(acc[2 * j], acc[2 * j + 1], h, l);
        g_ysbf_h[pbase + j * NPIX] = h;
        g_ysbf_l[pbase + j * NPIX] = l;
    }
}

// ---------------------------------------------------------------------------
// i2h: conv3x3 64->192 via bf16-split mma.m16n8k16. (unchanged)
// ---------------------------------------------------------------------------
#define I2H_SMEM_BYTES ((2 * 5184 + 2 * 4416) * 4)
__global__ __launch_bounds__(256) void i2h_k(int t, const float* __restrict__ bias)
{
    extern __shared__ uint32_t sm_u[];
    uint32_t* s_wh = sm_u;
    uint32_t* s_wl = s_wh + 5184;
    uint32_t* s_xh = s_wl + 5184;
    uint32_t* s_xl = s_xh + 4416;

    int tid = threadIdx.x;
    int lane = tid & 31;
    int g  = lane >> 2;
    int t4 = lane & 3;
    int wid = tid >> 5;
    int wm = wid >> 2;
    int wn = wid & 3;
    int ry = wn >> 1;
    int xoff = (wn & 1) * 64;

    int y0 = blockIdx.x * 2;
    int ocg = blockIdx.y;
    int m0 = ocg * 64;
    int b  = blockIdx.z;
    const uint32_t* inh = g_ysbf_h + (b * 192 + t * 32) * NPIX;
    const uint32_t* inl = g_ysbf_l + (b * 192 + t * 32) * NPIX;

    float acc[2][8][4];
    #pragma unroll
    for (int mt = 0; mt < 2; mt++)
        #pragma unroll
        for (int nt = 0; nt < 8; nt++)
            #pragma unroll
            for (int i = 0; i < 4; i++) acc[mt][nt][i] = 0.f;

    for (int chunk = 0; chunk < 4; chunk++) {
        __syncthreads();
        int wbase = (ocg * 4 + chunk) * 4608;
        for (int i = tid; i < 4608; i += 256) {
            int smi = (i >> 6) * 72 + (i & 63);
            s_wh[smi] = g_wi2h_h[wbase + i];
            s_wl[smi] = g_wi2h_l[wbase + i];
        }
        int pbase = chunk * 8;
        for (int i = tid; i < 4160; i += 256) {
            int col = i % 130, r = i / 130;
            int row = r & 3, kp = r >> 2;
            int gy = y0 - 1 + row, gx = col - 1;
            uint32_t vh = 0, vl = 0;
            if (gy >= 0 && gy < 128 && gx >= 0 && gx < 128) {
                int off = (pbase + kp) * NPIX + gy * 128 + gx;
                vh = inh[off]; vl = inl[off];
            }
            int si = kp * 552 + row * 136 + col;
            s_xh[si] = vh; s_xl[si] = vl;
        }
        __syncthreads();

        #pragma unroll
        for (int ky = 0; ky < 3; ky++) {
            #pragma unroll
            for (int kx = 0; kx < 3; kx++) {
                int tap = ky * 3 + kx;
                uint32_t ah[2][4], al[2][4];
                #pragma unroll
                for (int mt = 0; mt < 2; mt++) {
                    int mm = wm * 32 + mt * 16 + g;
                    int r0 = (tap * 8 + t4) * 72, r1 = (tap * 8 + t4 + 4) * 72;
                    ah[mt][0] = s_wh[r0 + mm];     ah[mt][1] = s_wh[r0 + mm + 8];
                    ah[mt][2] = s_wh[r1 + mm];     ah[mt][3] = s_wh[r1 + mm + 8];
                    al[mt][0] = s_wl[r0 + mm];     al[mt][1] = s_wl[r0 + mm + 8];
                    al[mt][2] = s_wl[r1 + mm];     al[mt][3] = s_wl[r1 + mm + 8];
                }
                int base = (ry + ky) * 136 + xoff + kx;
                #pragma unroll
                for (int nt = 0; nt < 8; nt++) {
                    int cc = base + nt * 8 + g;
                    uint32_t bh0 = s_xh[t4 * 552 + cc];
                    uint32_t bh1 = s_xh[(t4 + 4) * 552 + cc];
                    uint32_t bl0 = s_xl[t4 * 552 + cc];
                    uint32_t bl1 = s_xl[(t4 + 4) * 552 + cc];
                    #pragma unroll
                    for (int mt = 0; mt < 2; mt++) {
                        float* c = acc[mt][nt];
                        MMA_BF16(c[0], c[1], c[2], c[3],
                                 al[mt][0], al[mt][1], al[mt][2], al[mt][3], bh0, bh1);
                        MMA_BF16(c[0], c[1], c[2], c[3],
                                 ah[mt][0], ah[mt][1], ah[mt][2], ah[mt][3], bl0, bl1);
                        MMA_BF16(c[0], c[1], c[2], c[3],
                                 ah[mt][0], ah[mt][1], ah[mt][2], ah[mt][3], bh0, bh1);
                    }
                }
            }
        }
    }

    int pix0 = (y0 + ry) * 128 + xoff;
    #pragma unroll
    for (int mt = 0; mt < 2; mt++) {
        int m = m0 + wm * 32 + mt * 16 + g;
        float bb0 = bias[m], bb1 = bias[m + 8];
        float* C0 = &g_i2h[(b * 192 + m    ) * NPIX];
        float* C1 = &g_i2h[(b * 192 + m + 8) * NPIX];
        #pragma unroll
        for (int nt = 0; nt < 8; nt++) {
            int px = pix0 + nt * 8 + t4 * 2;
            *(float2*)&C0[px] = make_float2(acc[mt][nt][0] + bb0, acc[mt][nt][1] + bb0);
            *(float2*)&C1[px] = make_float2(acc[mt][nt][2] + bb1, acc[mt][nt][3] + bb1);
        }
    }
}

// ---------------------------------------------------------------------------
// f1: conv5x5 of one source (64 ic -> 32 oc), bf16-split TC. (unchanged)
// ---------------------------------------------------------------------------
#define C5_SMEM_BYTES ((2 * 8000 + 2 * 8768) * 4)
__global__ __launch_bounds__(256) void f1_k(int t, int first)
{
    int src = blockIdx.y;
    if (first && src) return;

    extern __shared__ uint32_t sm_u[];
    uint32_t* s_wh = sm_u;
    uint32_t* s_wl = s_wh + 8000;
    uint32_t* s_xh = s_wl + 8000;
    uint32_t* s_xl = s_xh + 8768;

    int tid = threadIdx.x;
    int lane = tid & 31;
    int g  = lane >> 2;
    int t4 = lane & 3;
    int wid = tid >> 5;
    int rw = wid >> 1;
    int xoff = (wid & 1) * 64;

    int y0 = blockIdx.x * 4;
    int b  = blockIdx.z;
    const uint32_t* inh = src ? (g_hbf_h + b * 32 * NPIX) : (g_ysbf_h + (b * 192 + t * 32) * NPIX);
    const uint32_t* inl = src ? (g_hbf_l + b * 32 * NPIX) : (g_ysbf_l + (b * 192 + t * 32) * NPIX);

    float acc[2][8][4];
    #pragma unroll
    for (int mt = 0; mt < 2; mt++)
        #pragma unroll
        for (int nt = 0; nt < 8; nt++)
            #pragma unroll
            for (int i = 0; i < 4; i++) acc[mt][nt][i] = 0.f;

    for (int chunk = 0; chunk < 4; chunk++) {
        __syncthreads();
        int wbase = (src * 4 + chunk) * 6400;
        for (int i = tid; i < 6400; i += 256) {
            int smi = (i >> 5) * 40 + (i & 31);
            s_wh[smi] = g_wf1_h[wbase + i];
            s_wl[smi] = g_wf1_l[wbase + i];
        }
        int pbase = chunk * 8;
        for (int i = tid; i < 8448; i += 256) {
            int col = i % 132, r = i / 132;
            int row = r & 7, kp = r >> 3;
            int gy = y0 - 2 + row, gx = col - 2;
            uint32_t vh = 0, vl = 0;
            if (gy >= 0 && gy < 128 && gx >= 0 && gx < 128) {
                int off = (pbase + kp) * NPIX + gy * 128 + gx;
                vh = inh[off]; vl = inl[off];
            }
            int si = kp * 1096 + row * 136 + col;
            s_xh[si] = vh; s_xl[si] = vl;
        }
        __syncthreads();

        #pragma unroll 1
        for (int ky = 0; ky < 5; ky++) {
            #pragma unroll
            for (int kx = 0; kx < 5; kx++) {
                int tap = ky * 5 + kx;
                uint32_t ah[2][4], al[2][4];
                #pragma unroll
                for (int mt = 0; mt < 2; mt++) {
                    int mm = mt * 16 + g;
                    int r0 = (tap * 8 + t4) * 40, r1 = (tap * 8 + t4 + 4) * 40;
                    ah[mt][0] = s_wh[r0 + mm];     ah[mt][1] = s_wh[r0 + mm + 8];
                    ah[mt][2] = s_wh[r1 + mm];     ah[mt][3] = s_wh[r1 + mm + 8];
                    al[mt][0] = s_wl[r0 + mm];     al[mt][1] = s_wl[r0 + mm + 8];
                    al[mt][2] = s_wl[r1 + mm];     al[mt][3] = s_wl[r1 + mm + 8];
                }
                int base = (rw + ky) * 136 + xoff + kx;
                #pragma unroll
                for (int nt = 0; nt < 8; nt++) {
                    int cc = base + nt * 8 + g;
                    uint32_t bh0 = s_xh[t4 * 1096 + cc];
                    uint32_t bh1 = s_xh[(t4 + 4) * 1096 + cc];
                    uint32_t bl0 = s_xl[t4 * 1096 + cc];
                    uint32_t bl1 = s_xl[(t4 + 4) * 1096 + cc];
                    #pragma unroll
                    for (int mt = 0; mt < 2; mt++) {
                        float* c = acc[mt][nt];
                        MMA_BF16(c[0], c[1], c[2], c[3],
                                 al[mt][0], al[mt][1], al[mt][2], al[mt][3], bh0, bh1);
                        MMA_BF16(c[0], c[1], c[2], c[3],
                                 ah[mt][0], ah[mt][1], ah[mt][2], ah[mt][3], bl0, bl1);
                        MMA_BF16(c[0], c[1], c[2], c[3],
                                 ah[mt][0], ah[mt][1], ah[mt][2], ah[mt][3], bh0, bh1);
                    }
                }
            }
        }
    }

    float* op = g_f1p[src];
    int pix0 = (y0 + rw) * 128 + xoff;
    #pragma unroll
    for (int mt = 0; mt < 2; mt++) {
        int m = mt * 16 + g;
        float* C0 = &op[(b * 32 + m    ) * NPIX];
        float* C1 = &op[(b * 32 + m + 8) * NPIX];
        #pragma unroll
        for (int nt = 0; nt < 8; nt++) {
            int px = pix0 + nt * 8 + t4 * 2;
            *(float2*)&C0[px] = make_float2(acc[mt][nt][0], acc[mt][nt][1]);
            *(float2*)&C1[px] = make_float2(acc[mt][nt][2], acc[mt][nt][3]);
        }
    }
}

// f1 combine: sum src partials + biases, leaky -> bf16-split pairs
__global__ void f1comb_k(const float* __restrict__ bi, const float* __restrict__ bh, int first)
{
    int idx = blockIdx.x * 256 + threadIdx.x;
    int pix = idx & (NPIX - 1);
    int c2  = (idx >> 14) & 15;
    int b   = idx >> 18;
    int c   = 2 * c2;
    int p0 = (b * 32 + c) * NPIX + pix;
    float v0 = g_f1p[0][p0];
    float v1 = g_f1p[0][p0 + NPIX];
    if (!first) { v0 += g_f1p[1][p0]; v1 += g_f1p[1][p0 + NPIX]; }
    v0 = leaky_f(v0 + bi[c] + bh[c]);
    v1 = leaky_f(v1 + bi[c + 1] + bh[c + 1]);
    uint32_t h, l;
    split2(v0, v1, h, l);
    g_f1bf_h[idx] = h; g_f1bf_l[idx] = l;
}

// ---------------------------------------------------------------------------
// flow: conv5x5 32 -> 26 (padded 32), bf16-split TC, writes g_fl + bias.
// ---------------------------------------------------------------------------
__global__ __launch_bounds__(256) void flow_k(const float* __restrict__ bias)
{
    extern __shared__ uint32_t sm_u[];
    uint32_t* s_wh = sm_u;
    uint32_t* s_wl = s_wh + 8000;
    uint32_t* s_xh = s_wl + 8000;
    uint32_t* s_xl = s_xh + 8768;

    int tid = threadIdx.x;
    int lane = tid & 31;
    int g  = lane >> 2;
    int t4 = lane & 3;
    int wid = tid >> 5;
    int rw = wid >> 1;
    int xoff = (wid & 1) * 64;

    int y0 = blockIdx.x * 4;
    int b  = blockIdx.z;
    const uint32_t* inh = g_f1bf_h + b * 16 * NPIX;
    const uint32_t* inl = g_f1bf_l + b * 16 * NPIX;

    float acc[2][8][4];
    #pragma unroll
    for (int mt = 0; mt < 2; mt++)
        #pragma unroll
        for (int nt = 0; nt < 8; nt++)
            #pragma unroll
            for (int i = 0; i < 4; i++) acc[mt][nt][i] = 0.f;

    for (int chunk = 0; chunk < 2; chunk++) {
        __syncthreads();
        int wbase = chunk * 6400;
        for (int i = tid; i < 6400; i += 256) {
            int smi = (i >> 5) * 40 + (i & 31);
            s_wh[smi] = g_wfl_h[wbase + i];
            s_wl[smi] = g_wfl_l[wbase + i];
        }
        int pbase = chunk * 8;
        for (int i = tid; i < 8448; i += 256) {
            int col = i % 132, r = i / 132;
            int row = r & 7, kp = r >> 3;
            int gy = y0 - 2 + row, gx = col - 2;
            uint32_t vh = 0, vl = 0;
            if (gy >= 0 && gy < 128 && gx >= 0 && gx < 128) {
                int off = (pbase + kp) * NPIX + gy * 128 + gx;
                vh = inh[off]; vl = inl[off];
            }
            int si = kp * 1096 + row * 136 + col;
            s_xh[si] = vh; s_xl[si] = vl;
        }
        __syncthreads();

        #pragma unroll 1
        for (int ky = 0; ky < 5; ky++) {
            #pragma unroll
            for (int kx = 0; kx < 5; kx++) {
                int tap = ky * 5 + kx;
                uint32_t ah[2][4], al[2][4];
                #pragma unroll
                for (int mt = 0; mt < 2; mt++) {
                    int mm = mt * 16 + g;
                    int r0 = (tap * 8 + t4) * 40, r1 = (tap * 8 + t4 + 4) * 40;
                    ah[mt][0] = s_wh[r0 + mm];     ah[mt][1] = s_wh[r0 + mm + 8];
                    ah[mt][2] = s_wh[r1 + mm];     ah[mt][3] = s_wh[r1 + mm + 8];
                    al[mt][0] = s_wl[r0 + mm];     al[mt][1] = s_wl[r0 + mm + 8];
                    al[mt][2] = s_wl[r1 + mm];     al[mt][3] = s_wl[r1 + mm + 8];
                }
                int base = (rw + ky) * 136 + xoff + kx;
                #pragma unroll
                for (int nt = 0; nt < 8; nt++) {
                    int cc = base + nt * 8 + g;
                    uint32_t bh0 = s_xh[t4 * 1096 + cc];
                    uint32_t bh1 = s_xh[(t4 + 4) * 1096 + cc];
                    uint32_t bl0 = s_xl[t4 * 1096 + cc];
                    uint32_t bl1 = s_xl[(t4 + 4) * 1096 + cc];
                    #pragma unroll
                    for (int mt = 0; mt < 2; mt++) {
                        float* c = acc[mt][nt];
                        MMA_BF16(c[0], c[1], c[2], c[3],
                                 al[mt][0], al[mt][1], al[mt][2], al[mt][3], bh0, bh1);
                        MMA_BF16(c[0], c[1], c[2], c[3],
                                 ah[mt][0], ah[mt][1], ah[mt][2], ah[mt][3], bl0, bl1);
                        MMA_BF16(c[0], c[1], c[2], c[3],
                                 ah[mt][0], ah[mt][1], ah[mt][2], ah[mt][3], bh0, bh1);
                    }
                }
            }
        }
    }

    int pix0 = (y0 + rw) * 128 + xoff;
    #pragma unroll
    for (int mt = 0; mt < 2; mt++) {
        int m = mt * 16 + g;
        #pragma unroll
        for (int nt = 0; nt < 8; nt++) {
            int px = pix0 + nt * 8 + t4 * 2;
            if (m < 26) {
                float bb = bias[m];
                *(float2*)&g_fl[(b * 26 + m) * NPIX + px] =
                    make_float2(acc[mt][nt][0] + bb, acc[mt][nt][1] + bb);
            }
            if (m + 8 < 26) {
                float bb = bias[m + 8];
                *(float2*)&g_fl[(b * 26 + m + 8) * NPIX + px] =
                    make_float2(acc[mt][nt][2] + bb, acc[mt][nt][3] + bb);
            }
        }
    }
}

// ---------------------------------------------------------------------------
// wret: fused warp + ret. C[192,16384] = W[192,832] * warp(hprev)[832,16384].
// B tile built in-kernel: bilinear gather of hprev (L2-resident) per k-chunk,
// bf16-split, fed to mma.m16n8k16. BM=96, BN=128. grid (128, 2, 2).
// ---------------------------------------------------------------------------
__global__ __launch_bounds__(256, 2) void wret_k(int t, const float* __restrict__ bias,
                                                 int first, const float* __restrict__ outp)
{
    __shared__ int      s_ci[4][128];
    __shared__ float    s_cw[4][128];
    __shared__ uint32_t s_wh[8 * 104], s_wl[8 * 104];
    __shared__ uint32_t s_bh[8 * 136], s_bl[8 * 136];

    int tid = threadIdx.x;
    int lane = tid & 31;
    int g  = lane >> 2;
    int t4 = lane & 3;
    int wid = tid >> 5;
    int wm = wid >> 2;
    int wn = wid & 3;
    int mb = wm * 48;
    int nb = wn * 32;

    int b  = blockIdx.z;
    int n0 = blockIdx.x * 128;
    int mblk = blockIdx.y;
    int m0 = mblk * 96;

    float acc[3][4][4];
    #pragma unroll
    for (int mt = 0; mt < 3; mt++)
        #pragma unroll
        for (int nt = 0; nt < 4; nt++)
            #pragma unroll
            for (int i = 0; i < 4; i++) acc[mt][nt][i] = 0.f;

    if (!first) {
        const float* hprev = outp + ((b * 6 + (t - 1)) * 64) * NPIX;

        for (int l = 0; l < 13; l++) {
            __syncthreads();
            if (tid < 128) {
                int pg = n0 + tid;
                float u = g_fl[(b * 26 + 2 * l    ) * NPIX + pg];
                float v = g_fl[(b * 26 + 2 * l + 1) * NPIX + pg];
                float sx = (float)(pg & 127) - u;
                float sy = (float)(pg >> 7)  - v;
                float fx = floorf(sx), fy = floorf(sy);
                float wx1 = sx - fx, wx0 = 1.f - wx1;
                float wy1 = sy - fy, wy0 = 1.f - wy1;
                int x0 = (int)fx, y0 = (int)fy;
                int x1 = x0 + 1,  y1 = y0 + 1;
                bool vx0 = (x0 >= 0) & (x0 <= 127);
                bool vx1 = (x1 >= 0) & (x1 <= 127);
                bool vy0 = (y0 >= 0) & (y0 <= 127);
                bool vy1 = (y1 >= 0) & (y1 <= 127);
                int cx0 = min(max(x0, 0), 127), cx1 = min(max(x1, 0), 127);
                int cy0 = min(max(y0, 0), 127), cy1 = min(max(y1, 0), 127);
                s_ci[0][tid] = cy0 * 128 + cx0;
                s_ci[1][tid] = cy0 * 128 + cx1;
                s_ci[2][tid] = cy1 * 128 + cx0;
                s_ci[3][tid] = cy1 * 128 + cx1;
                s_cw[0][tid] = (vx0 && vy0) ? wx0 * wy0 : 0.f;
                s_cw[1][tid] = (vx1 && vy0) ? wx1 * wy0 : 0.f;
                s_cw[2][tid] = (vx0 && vy1) ? wx0 * wy1 : 0.f;
                s_cw[3][tid] = (vx1 && vy1) ? wx1 * wy1 : 0.f;
            }

            for (int chunk = 0; chunk < 4; chunk++) {
                __syncthreads();
                // A chunk: 8 kp x 96 m
                int wbase = ((mblk * 13 + l) * 4 + chunk) * 768;
                #pragma unroll
                for (int r = 0; r < 3; r++) {
                    int i = tid + r * 256;
                    int smi = (i / 96) * 104 + (i % 96);
                    s_wh[smi] = g_wret_h[wbase + i];
                    s_wl[smi] = g_wret_l[wbase + i];
                }
                // B chunk: gather + split, 8 kp x 128 px
                #pragma unroll
                for (int r = 0; r < 4; r++) {
                    int j = tid + r * 256;
                    int kp = j >> 7, px = j & 127;
                    int i00 = s_ci[0][px], i10 = s_ci[1][px];
                    int i01 = s_ci[2][px], i11 = s_ci[3][px];
                    float w00 = s_cw[0][px], w10 = s_cw[1][px];
                    float w01 = s_cw[2][px], w11 = s_cw[3][px];
                    const float* h0 = hprev + (chunk * 16 + kp * 2) * NPIX;
                    const float* h1 = h0 + NPIX;
                    float v0 = w00 * __ldg(&h0[i00]) + w10 * __ldg(&h0[i10])
                             + w01 * __ldg(&h0[i01]) + w11 * __ldg(&h0[i11]);
                    float v1 = w00 * __ldg(&h1[i00]) + w10 * __ldg(&h1[i10])
                             + w01 * __ldg(&h1[i01]) + w11 * __ldg(&h1[i11]);
                    uint32_t hh, ll;
                    split2(v0, v1, hh, ll);
                    s_bh[kp * 136 + px] = hh;
                    s_bl[kp * 136 + px] = ll;
                }
                __syncthreads();

                uint32_t ah[3][4], al[3][4], bh[4][2], bl[4][2];
                #pragma unroll
                for (int mt = 0; mt < 3; mt++) {
                    int mm = mb + mt * 16 + g;
                    int r0 = t4 * 104, r1 = (t4 + 4) * 104;
                    ah[mt][0] = s_wh[r0 + mm];     ah[mt][1] = s_wh[r0 + mm + 8];
                    ah[mt][2] = s_wh[r1 + mm];     ah[mt][3] = s_wh[r1 + mm + 8];
                    al[mt][0] = s_wl[r0 + mm];     al[mt][1] = s_wl[r0 + mm + 8];
                    al[mt][2] = s_wl[r1 + mm];     al[mt][3] = s_wl[r1 + mm + 8];
                }
                #pragma unroll
                for (int nt = 0; nt < 4; nt++) {
                    int nn = nb + nt * 8 + g;
                    bh[nt][0] = s_bh[t4 * 136 + nn];
                    bh[nt][1] = s_bh[(t4 + 4) * 136 + nn];
                    bl[nt][0] = s_bl[t4 * 136 + nn];
                    bl[nt][1] = s_bl[(t4 + 4) * 136 + nn];
                }
                #pragma unroll
                for (int mt = 0; mt < 3; mt++)
                    #pragma unroll
                    for (int nt = 0; nt < 4; nt++) {
                        float* c = acc[mt][nt];
                        MMA_BF16(c[0], c[1], c[2], c[3],
                                 al[mt][0], al[mt][1], al[mt][2], al[mt][3],
                                 bh[nt][0], bh[nt][1]);
                        MMA_BF16(c[0], c[1], c[2], c[3],
                                 ah[mt][0], ah[mt][1], ah[mt][2], ah[mt][3],
                                 bl[nt][0], bl[nt][1]);
                        MMA_BF16(c[0], c[1], c[2], c[3],
                                 ah[mt][0], ah[mt][1], ah[mt][2], ah[mt][3],
                                 bh[nt][0], bh[nt][1]);
                    }
            }
        }
    }

    float* C = g_h2h + b * 192 * NPIX;
    #pragma unroll
    for (int mt = 0; mt < 3; mt++) {
        int m = m0 + mb + mt * 16 + g;
        float bb0 = bias[m], bb1 = bias[m + 8];
        #pragma unroll
        for (int nt = 0; nt < 4; nt++) {
            int col = n0 + nb + nt * 8 + t4 * 2;
            float2 o0 = make_float2(acc[mt][nt][0] + bb0, acc[mt][nt][1] + bb0);
            float2 o1 = make_float2(acc[mt][nt][2] + bb1, acc[mt][nt][3] + bb1);
            *(float2*)&C[m * NPIX + col]       = o0;
            *(float2*)&C[(m + 8) * NPIX + col] = o1;
        }
    }
}

// ---------------------------------------------------------------------------
// GRU update: writes out[b,t] fp32 + bf16-split hidden copy (channel pairs).
// ---------------------------------------------------------------------------
__global__ void gru_k(int t, int first, float* __restrict__ outp)
{
    int pix = blockIdx.x * 256 + threadIdx.x;
    int c2  = blockIdx.y;
    int b   = blockIdx.z;
    int c   = 2 * c2;
    int base = b * 192 * NPIX;

    float h01[2];
    #pragma unroll
    for (int j = 0; j < 2; j++) {
        int cj = c + j;
        float ir = g_i2h[base + (cj      ) * NPIX + pix];
        float iu = g_i2h[base + (cj +  64) * NPIX + pix];
        float im = g_i2h[base + (cj + 128) * NPIX + pix];
        float hr = g_h2h[base + (cj      ) * NPIX + pix];
        float hu = g_h2h[base + (cj +  64) * NPIX + pix];
        float hm = g_h2h[base + (cj + 128) * NPIX + pix];

        float r = 1.f / (1.f + expf(-(ir + hr)));
        float z = 1.f / (1.f + expf(-(iu + hu)));
        float m = leaky_f(im + r * hm);

        float hp = first ? 0.f : outp[((b * 6 + t - 1) * 64 + cj) * NPIX + pix];
        float h  = z * hp + (1.f - z) * m;
        outp[((b * 6 + t) * 64 + cj) * NPIX + pix] = h;
        h01[j] = h;
    }
    uint32_t hw, lw;
    split2(h01[0], h01[1], hw, lw);
    int p = (b * 32 + c2) * NPIX + pix;
    g_hbf_h[p] = hw; g_hbf_l[p] = lw;
}

// ---------------------------------------------------------------------------
// Launch
// ---------------------------------------------------------------------------
extern "C" void kernel_launch(void* const* d_in, const int* in_sizes, int n_in,
                              void* d_out, int out_size)
{
    const float* x      = (const float*)d_in[0];
    const float* w_stem = (const float*)d_in[1];
    const float* b_stem = (const float*)d_in[2];
    const float* w_i2h  = (const float*)d_in[3];
    const float* b_i2h  = (const float*)d_in[4];
    const float* w_i2f  = (const float*)d_in[5];
    const float* b_i2f  = (const float*)d_in[6];
    const float* w_h2f  = (const float*)d_in[7];
    const float* b_h2f  = (const float*)d_in[8];
    const float* w_flow = (const float*)d_in[9];
    const float* b_flow = (const float*)d_in[10];
    const float* w_ret  = (const float*)d_in[11];
    const float* b_ret  = (const float*)d_in[12];
    float* outp = (float*)d_out;

    cudaFuncSetAttribute(i2h_k,  cudaFuncAttributeMaxDynamicSharedMemorySize, I2H_SMEM_BYTES);
    cudaFuncSetAttribute(f1_k,   cudaFuncAttributeMaxDynamicSharedMemorySize, C5_SMEM_BYTES);
    cudaFuncSetAttribute(flow_k, cudaFuncAttributeMaxDynamicSharedMemorySize, C5_SMEM_BYTES);

    wprep_i2h_k<<<(55296 + 255) / 256, 256>>>(w_i2h);
    wprep_f1_k <<<(51200 + 255) / 256, 256>>>(w_i2f, w_h2f);
    wprep_fl_k <<<(12800 + 255) / 256, 256>>>(w_flow);
    wprep_ret_k<<<(79872 + 255) / 256, 256>>>(w_ret);

    stem_k<<<dim3(64, 48, 2), 256>>>(x, w_stem, b_stem);

    for (int t = 0; t < 6; t++) {
        int first = (t == 0) ? 1 : 0;
        i2h_k   <<<dim3(64, 3, 2), 256, I2H_SMEM_BYTES>>>(t, b_i2h);
        f1_k    <<<dim3(32, 2, 2), 256, C5_SMEM_BYTES>>>(t, first);
        f1comb_k<<<(2 * 16 * NPIX) / 256, 256>>>(b_i2f, b_h2f, first);
        flow_k  <<<dim3(32, 1, 2), 256, C5_SMEM_BYTES>>>(b_flow);
        wret_k  <<<dim3(128, 2, 2), 256>>>(t, b_ret, first, outp);
        gru_k   <<<dim3(64, 32, 2), 256>>>(t, first, outp);
    }
}